// round 8
// baseline (speedup 1.0000x reference)
#include <cuda_runtime.h>

#define F 64
#define NT 8
#define NWARP 4            // 128-thread blocks

// Node counts (fixed by the problem)
#define N_HIT 300000
#define N_SP   50000
#define N_OPH 200000
#define N_PMT  30000
#define N_OPF   2000
#define N_EVT    256

#define CTOT 660000
#define ETOT 1510000
#define DTOT 600000

// ---- scratch (device globals) ----
__device__ float g_acc[(size_t)(N_OPF + N_EVT) * 128];
__device__ float g_nbuf[(size_t)N_SP * F];
__device__ float g_pmtbuf[(size_t)N_PMT * F];
__device__ float g_opfbuf[(size_t)N_OPF * F];
__device__ int   g_count[CTOT];
__device__ int   g_offs[CTOT];
__device__ int   g_cursor[CTOT];
__device__ int   g_ssrc[ETOT];
__device__ int   g_bsums[128];
__device__ float g_dotj[DTOT];

__device__ __forceinline__ float2 ffma2(float2 a, float2 b, float2 c) {
    unsigned long long ua = *reinterpret_cast<unsigned long long*>(&a);
    unsigned long long ub = *reinterpret_cast<unsigned long long*>(&b);
    unsigned long long uc = *reinterpret_cast<unsigned long long*>(&c);
    unsigned long long ud;
    asm("fma.rn.f32x2 %0, %1, %2, %3;" : "=l"(ud) : "l"(ua), "l"(ub), "l"(uc));
    return *reinterpret_cast<float2*>(&ud);
}

__device__ __forceinline__ float mishf(float x) {
    float e = __expf(fminf(x, 30.f));
    float t = e * (e + 2.f);
    return x * __fdividef(t, t + 2.f);
}

// ======================= batched sort machinery =======================

struct SortCfg {
    const int* src[4];
    const int* dst[4];
    int ebase[5];   // relative edge prefix (0-based within this sort job)
    int cbase[4];   // absolute target-count bases
};

__global__ void zero_k(int* __restrict__ p, int n) {
    int i = blockIdx.x * blockDim.x + threadIdx.x;
    for (; i < n; i += gridDim.x * blockDim.x) p[i] = 0;
}

__global__ void hist_all(SortCfg cfg, int Etot, int* __restrict__ cnt) {
    int i = blockIdx.x * blockDim.x + threadIdx.x;
    if (i >= Etot) return;
    int s = 0;
    while (i >= cfg.ebase[s + 1]) s++;
    int li = i - cfg.ebase[s];
    atomicAdd(&cnt[cfg.cbase[s] + cfg.dst[s][li]], 1);
}

#define SCHUNK 8192
// processes cnt[cbeg : cend), one block per SCHUNK chunk
__global__ void scan1_k(const int* __restrict__ cnt, int cbeg, int cend, int* __restrict__ bsums) {
    __shared__ int ts[256];
    int tid = threadIdx.x;
    int base = cbeg + blockIdx.x * SCHUNK;
    int s = 0;
#pragma unroll
    for (int j = 0; j < 32; j++) {
        int i = base + j * 256 + tid;
        if (i < cend) s += cnt[i];
    }
    ts[tid] = s; __syncthreads();
    for (int o = 128; o; o >>= 1) { if (tid < o) ts[tid] += ts[tid + o]; __syncthreads(); }
    if (!tid) bsums[blockIdx.x] = ts[0];
}

__global__ void scan2_k(int* __restrict__ bsums, int nb, int base) {
    __shared__ int sb[128];
    int tid = threadIdx.x;
    if (tid < nb) sb[tid] = bsums[tid];
    __syncthreads();
    if (tid == 0) {
        int run = base;
        for (int b = 0; b < nb; b++) { int t = sb[b]; sb[b] = run; run += t; }
    }
    __syncthreads();
    if (tid < nb) bsums[tid] = sb[tid];
}

__global__ void scan3_k(const int* __restrict__ cnt, const int* __restrict__ bsums,
                        int cbeg, int cend, int* __restrict__ offs, int* __restrict__ cur) {
    __shared__ int ts[256];
    int tid = threadIdx.x;
    int base = cbeg + blockIdx.x * SCHUNK + tid * 32;
    int v[32]; int s = 0;
#pragma unroll
    for (int j = 0; j < 32; j++) {
        int i = base + j;
        v[j] = (i < cend) ? cnt[i] : 0;
        s += v[j];
    }
    ts[tid] = s; __syncthreads();
    for (int off = 1; off < 256; off <<= 1) {
        int add = (tid >= off) ? ts[tid - off] : 0;
        __syncthreads();
        ts[tid] += add;
        __syncthreads();
    }
    int run = (tid ? ts[tid - 1] : 0) + bsums[blockIdx.x];
#pragma unroll
    for (int j = 0; j < 32; j++) {
        int i = base + j;
        if (i < cend) { offs[i] = run; cur[i] = run; run += v[j]; }
    }
}

// cur holds ABSOLUTE positions into ssrc; writes are absolute.
__global__ void scatter_all(SortCfg cfg, int Etot, int* __restrict__ cur, int* __restrict__ ssrc) {
    int i = blockIdx.x * blockDim.x + threadIdx.x;
    if (i >= Etot) return;
    int s = 0;
    while (i >= cfg.ebase[s + 1]) s++;
    int li = i - cfg.ebase[s];
    int pos = atomicAdd(&cur[cfg.cbase[s] + cfg.dst[s][li]], 1);
    ssrc[pos] = cfg.src[s][li];
}

__global__ void dotj_k(const float* __restrict__ xsrc, int n_src,
                       const float* __restrict__ eW, float* __restrict__ dotj) {
    int lane = threadIdx.x & 31;
    int node = (blockIdx.x * blockDim.x + threadIdx.x) >> 5;
    float wj0 = eW[64 + 2 * lane], wj1 = eW[65 + 2 * lane];
    if (node >= n_src) return;
    float2 x = *reinterpret_cast<const float2*>(xsrc + (size_t)node * F + 2 * lane);
    float p = x.x * wj0 + x.y * wj1;
#pragma unroll
    for (int o = 16; o; o >>= 1) p += __shfl_xor_sync(0xffffffffu, p, o);
    if (!lane) dotj[node] = p;
}

// ======================= shared MLP helpers =======================
// smem floats: [0:8192) w1 packed, [8192:12288) w2 packed, [12288:12352) b1,
// [12352:12416) b2, [12416:...) cat buffers (NWARP * NT * 128 float2 = 32KB)

__device__ __forceinline__ void load_weights(float* sm, const float* __restrict__ w1,
                                             const float* __restrict__ b1,
                                             const float* __restrict__ w2,
                                             const float* __restrict__ b2, int tid, int nthr) {
    float4* w1p = reinterpret_cast<float4*>(sm);
    float4* w2p = reinterpret_cast<float4*>(sm + 8192);
    for (int e = tid; e < 2048; e += nthr) {
        int kk = e >> 5, l = e & 31;
        float2 a = *reinterpret_cast<const float2*>(w1 + (2 * kk) * 64 + 2 * l);
        float2 b = *reinterpret_cast<const float2*>(w1 + (2 * kk + 1) * 64 + 2 * l);
        w1p[e] = make_float4(a.x, a.y, b.x, b.y);
    }
    for (int e = tid; e < 1024; e += nthr) {
        int kk = e >> 5, l = e & 31;
        float2 a = *reinterpret_cast<const float2*>(w2 + (2 * kk) * 64 + 2 * l);
        float2 b = *reinterpret_cast<const float2*>(w2 + (2 * kk + 1) * 64 + 2 * l);
        w2p[e] = make_float4(a.x, a.y, b.x, b.y);
    }
    if (tid < 64) { sm[12288 + tid] = b1[tid]; sm[12352 + tid] = b2[tid]; }
}

__device__ __forceinline__ void mlp_apply(const float* sm, float2* cw, int lane, float2 o[NT]) {
    const float4* w1p = reinterpret_cast<const float4*>(sm);
    const float4* w2p = reinterpret_cast<const float4*>(sm + 8192);
    float2 acc[NT];
    float2 bv1 = *reinterpret_cast<const float2*>(sm + 12288 + 2 * lane);
#pragma unroll
    for (int t = 0; t < NT; t++) acc[t] = bv1;
#pragma unroll 2
    for (int kk = 0; kk < 64; kk++) {
        float4 wv = w1p[kk * 32 + lane];
#pragma unroll
        for (int t = 0; t < NT; t++) {
            float4 cv = *reinterpret_cast<const float4*>(cw + t * 128 + 2 * kk);
            acc[t] = ffma2(make_float2(wv.x, wv.y), make_float2(cv.x, cv.y), acc[t]);
            acc[t] = ffma2(make_float2(wv.z, wv.w), make_float2(cv.z, cv.w), acc[t]);
        }
    }
    __syncwarp();
#pragma unroll
    for (int t = 0; t < NT; t++) {
        float h0 = mishf(acc[t].x), h1 = mishf(acc[t].y);
        cw[t * 128 + 2 * lane]     = make_float2(h0, h0);
        cw[t * 128 + 2 * lane + 1] = make_float2(h1, h1);
    }
    __syncwarp();
    float2 bv2 = *reinterpret_cast<const float2*>(sm + 12352 + 2 * lane);
#pragma unroll
    for (int t = 0; t < NT; t++) acc[t] = bv2;
#pragma unroll 2
    for (int kk = 0; kk < 32; kk++) {
        float4 wv = w2p[kk * 32 + lane];
#pragma unroll
        for (int t = 0; t < NT; t++) {
            float4 cv = *reinterpret_cast<const float4*>(cw + t * 128 + 2 * kk);
            acc[t] = ffma2(make_float2(wv.x, wv.y), make_float2(cv.x, cv.y), acc[t]);
            acc[t] = ffma2(make_float2(wv.z, wv.w), make_float2(cv.z, cv.w), acc[t]);
        }
    }
#pragma unroll
    for (int t = 0; t < NT; t++) o[t] = make_float2(mishf(acc[t].x), mishf(acc[t].y));
}

// ======================= fused segment-reduce + MLP =======================
__global__ void __launch_bounds__(128, 2) fused_pass(
    const float* __restrict__ xsrc, const float* __restrict__ xtgt, int n_tgt,
    const int* __restrict__ ssrc, const int* __restrict__ offs, const int* __restrict__ cnt,
    const float* __restrict__ dotj,
    const float* __restrict__ eW, const float* __restrict__ eB,
    const float* __restrict__ w1, const float* __restrict__ b1,
    const float* __restrict__ w2, const float* __restrict__ b2,
    float* __restrict__ out) {
    extern __shared__ float sm[];
    float2* cats = reinterpret_cast<float2*>(sm + 12416);

    int tid = threadIdx.x;
    load_weights(sm, w1, b1, w2, b2, tid, 128);
    __syncthreads();

    int warp = tid >> 5, lane = tid & 31;
    float wi0 = eW[2 * lane], wi1 = eW[2 * lane + 1];
    float bia = eB[0];
    float2* cw = cats + warp * NT * 128;
    int stride = gridDim.x * NWARP * NT;

    for (int base = (blockIdx.x * NWARP + warp) * NT; base < n_tgt; base += stride) {
        int nv = n_tgt - base; if (nv > NT) nv = NT;

        int o[NT], c[NT];
        float2 xiv[NT];
        float dot_i[NT];
#pragma unroll
        for (int t = 0; t < NT; t++) {
            bool v = (t < nv);
            size_t node = (size_t)(base + t);
            o[t] = v ? offs[node] : 0;
            c[t] = v ? cnt[node]  : 0;
            xiv[t] = v ? *reinterpret_cast<const float2*>(xtgt + node * F + 2 * lane)
                       : make_float2(0.f, 0.f);
            float p = xiv[t].x * wi0 + xiv[t].y * wi1;
#pragma unroll
            for (int off = 16; off; off >>= 1) p += __shfl_xor_sync(0xffffffffu, p, off);
            dot_i[t] = p + bia;
        }

        int maxc = c[0];
#pragma unroll
        for (int t = 1; t < NT; t++) maxc = max(maxc, c[t]);

        float den0[NT], num0[NT], den1[NT], num1[NT];
#pragma unroll
        for (int t = 0; t < NT; t++) { den0[t] = 0.f; num0[t] = 0.f; den1[t] = 0.f; num1[t] = 0.f; }

        for (int k = 0; k < maxc; k++) {
            float  djv[NT];
            float2 xjv[NT];
#pragma unroll
            for (int t = 0; t < NT; t++) {
                if (k < c[t]) {
                    int s = ssrc[o[t] + k];
                    djv[t] = dotj[s];
                    xjv[t] = *reinterpret_cast<const float2*>(xsrc + (size_t)s * F + 2 * lane);
                }
            }
#pragma unroll
            for (int t = 0; t < NT; t++) {
                if (k < c[t]) {
                    float z = dot_i[t] + djv[t];
                    float w = __fdividef(1.f, 1.f + __expf(-z));
                    float m0 = w * xjv[t].x, m1 = w * xjv[t].y;
                    float e0 = __expf(m0),   e1 = __expf(m1);
                    den0[t] += e0; num0[t] += e0 * m0;
                    den1[t] += e1; num1[t] += e1 * m1;
                }
            }
        }

#pragma unroll
        for (int t = 0; t < NT; t++) {
            float a0 = __fdividef(num0[t], den0[t] + 1e-16f);
            float a1 = __fdividef(num1[t], den1[t] + 1e-16f);
            cw[t * 128 + 2 * lane]          = make_float2(a0, a0);
            cw[t * 128 + 2 * lane + 1]      = make_float2(a1, a1);
            cw[t * 128 + 64 + 2 * lane]     = make_float2(xiv[t].x, xiv[t].x);
            cw[t * 128 + 64 + 2 * lane + 1] = make_float2(xiv[t].y, xiv[t].y);
        }
        __syncwarp();

        float2 ov[NT];
        mlp_apply(sm, cw, lane, ov);

#pragma unroll
        for (int t = 0; t < NT; t++) {
            if (t < nv) {
                *reinterpret_cast<float2*>(out + (size_t)(base + t) * F + 2 * lane) = ov[t];
            }
        }
        __syncwarp();
    }
}

// ======================= small-pass atomic path =======================

__global__ void edge_pass(const float* __restrict__ xsrc, const float* __restrict__ xtgt,
                          const int* __restrict__ src, const int* __restrict__ dst, int E,
                          const float* __restrict__ eW, const float* __restrict__ eB,
                          float* __restrict__ acc) {
    __shared__ float Ws[2 * F];
    __shared__ float Bs;
    int tid = threadIdx.x;
    if (tid < 2 * F) Ws[tid] = eW[tid];
    if (tid == 0) Bs = eB[0];
    __syncthreads();

    int lane = tid & 31;
    int e = blockIdx.x * (blockDim.x >> 5) + (tid >> 5);
    if (e >= E) return;

    int s = src[e], d = dst[e];
    float2 xj = *reinterpret_cast<const float2*>(xsrc + (size_t)s * F + 2 * lane);
    float2 xi = *reinterpret_cast<const float2*>(xtgt + (size_t)d * F + 2 * lane);

    float part = xi.x * Ws[2 * lane] + xi.y * Ws[2 * lane + 1]
               + xj.x * Ws[F + 2 * lane] + xj.y * Ws[F + 2 * lane + 1];
#pragma unroll
    for (int o = 16; o; o >>= 1) part += __shfl_xor_sync(0xffffffffu, part, o);

    float w = __fdividef(1.f, 1.f + __expf(-(part + Bs)));
    float m0 = w * xj.x, m1 = w * xj.y;
    float e0 = __expf(m0), e1 = __expf(m1);

    float4 v = make_float4(e0, e0 * m0, e1, e1 * m1);
    atomicAdd(reinterpret_cast<float4*>(acc + (size_t)d * 128 + 4 * lane), v);
}

__global__ void __launch_bounds__(128, 2) node_pass(
    const float* __restrict__ xtgt, int n_tgt,
    const float* __restrict__ w1, const float* __restrict__ b1,
    const float* __restrict__ w2, const float* __restrict__ b2,
    float* __restrict__ out, int accumulate, float* __restrict__ accbuf) {
    extern __shared__ float sm[];
    float2* cats = reinterpret_cast<float2*>(sm + 12416);

    int tid = threadIdx.x;
    load_weights(sm, w1, b1, w2, b2, tid, 128);
    __syncthreads();

    int warp = tid >> 5, lane = tid & 31;
    float2* cw = cats + warp * NT * 128;
    int stride = gridDim.x * NWARP * NT;

    for (int base = (blockIdx.x * NWARP + warp) * NT; base < n_tgt; base += stride) {
        int nv = n_tgt - base; if (nv > NT) nv = NT;

#pragma unroll
        for (int t = 0; t < NT; t++) {
            if (t < nv) {
                size_t node = (size_t)(base + t);
                float4* ap = reinterpret_cast<float4*>(accbuf + node * 128 + 4 * lane);
                float4 a = *ap;
                *ap = make_float4(0.f, 0.f, 0.f, 0.f);  // self-clean for replay
                float2 xt = *reinterpret_cast<const float2*>(xtgt + node * F + 2 * lane);
                float a0 = __fdividef(a.y, a.x + 1e-16f);
                float a1 = __fdividef(a.w, a.z + 1e-16f);
                cw[t * 128 + 2 * lane]          = make_float2(a0, a0);
                cw[t * 128 + 2 * lane + 1]      = make_float2(a1, a1);
                cw[t * 128 + 64 + 2 * lane]     = make_float2(xt.x, xt.x);
                cw[t * 128 + 64 + 2 * lane + 1] = make_float2(xt.y, xt.y);
            }
        }
        __syncwarp();

        float2 ov[NT];
        mlp_apply(sm, cw, lane, ov);

#pragma unroll
        for (int t = 0; t < NT; t++) {
            if (t < nv) {
                float2* op = reinterpret_cast<float2*>(out + (size_t)(base + t) * F + 2 * lane);
                float2 o = ov[t];
                if (accumulate) { float2 pv = *op; o.x += pv.x; o.y += pv.y; }
                *op = o;
            }
        }
        __syncwarp();
    }
}

// ======================= launcher =======================

extern "C" void kernel_launch(void* const* d_in, const int* in_sizes, int n_in,
                              void* d_out, int out_size) {
    const float* x_hit = (const float*)d_in[0];
    const float* x_sp  = (const float*)d_in[1];
    const float* x_oph = (const float*)d_in[2];
    const float* x_pmt = (const float*)d_in[3];
    const float* x_opf = (const float*)d_in[4];
    const float* x_evt = (const float*)d_in[5];
    const float* ew = (const float*)d_in[6];
    const float* eb = (const float*)d_in[7];
    const float* w1 = (const float*)d_in[8];
    const float* b1 = (const float*)d_in[9];
    const float* w2 = (const float*)d_in[10];
    const float* b2 = (const float*)d_in[11];
    const int* e_hit_sp  = (const int*)d_in[12];
    const int* e_oph_pmt = (const int*)d_in[13];
    const int* e_pmt_opf = (const int*)d_in[14];
    const int* e_sp_evt  = (const int*)d_in[15];
    const int* e_opf_evt = (const int*)d_in[16];
    const int* e_evt_sp  = (const int*)d_in[17];
    const int* e_sp_hit  = (const int*)d_in[18];
    const int* e_evt_opf = (const int*)d_in[19];
    const int* e_opf_pmt = (const int*)d_in[20];
    const int* e_pmt_oph = (const int*)d_in[21];

    float* out = (float*)d_out;
    float* d_p   = out;
    float* d_n   = d_p   + (size_t)N_HIT * F;
    float* d_oph = d_n   + (size_t)N_SP  * F;
    float* d_pmt = d_oph + (size_t)N_OPH * F;
    float* d_opf = d_pmt + (size_t)N_PMT * F;
    float* d_i   = d_opf + (size_t)N_OPF * F;

    float *pacc, *pn, *ppmt, *popf, *pdotj;
    int *pcnt, *poffs, *pcur, *pssrc, *pbs;
    cudaGetSymbolAddress((void**)&pacc,  g_acc);
    cudaGetSymbolAddress((void**)&pn,    g_nbuf);
    cudaGetSymbolAddress((void**)&ppmt,  g_pmtbuf);
    cudaGetSymbolAddress((void**)&popf,  g_opfbuf);
    cudaGetSymbolAddress((void**)&pdotj, g_dotj);
    cudaGetSymbolAddress((void**)&pcnt,  g_count);
    cudaGetSymbolAddress((void**)&poffs, g_offs);
    cudaGetSymbolAddress((void**)&pcur,  g_cursor);
    cudaGetSymbolAddress((void**)&pssrc, g_ssrc);
    cudaGetSymbolAddress((void**)&pbs,   g_bsums);

    float* acc_opf = pacc;                          // p2, p7
    float* acc_evt = pacc + (size_t)N_OPF * 128;    // p3, p4

    const int SMEM = 82432;  // 12416 floats + NWARP*NT*128 float2 (32KB)
    cudaFuncSetAttribute(node_pass,  cudaFuncAttributeMaxDynamicSharedMemorySize, SMEM);
    cudaFuncSetAttribute(fused_pass, cudaFuncAttributeMaxDynamicSharedMemorySize, SMEM);

    static cudaStream_t s1 = nullptr, s2 = nullptr;
    static cudaEvent_t evRoot = nullptr, evSA = nullptr, evB = nullptr, evD = nullptr,
                       evE = nullptr, evSB = nullptr, evF = nullptr;
    if (!s1) {
        cudaStreamCreateWithFlags(&s1, cudaStreamNonBlocking);
        cudaStreamCreateWithFlags(&s2, cudaStreamNonBlocking);
        cudaEventCreateWithFlags(&evRoot, cudaEventDisableTiming);
        cudaEventCreateWithFlags(&evSA, cudaEventDisableTiming);
        cudaEventCreateWithFlags(&evB, cudaEventDisableTiming);
        cudaEventCreateWithFlags(&evD, cudaEventDisableTiming);
        cudaEventCreateWithFlags(&evE, cudaEventDisableTiming);
        cudaEventCreateWithFlags(&evSB, cudaEventDisableTiming);
        cudaEventCreateWithFlags(&evF, cudaEventDisableTiming);
    }
    cudaStream_t s0 = 0;

    int E0 = in_sizes[12] / 2;
    int E1 = in_sizes[13] / 2;
    int E2 = in_sizes[14] / 2;
    int E3 = in_sizes[15] / 2;
    int E4 = in_sizes[16] / 2;
    int E5 = in_sizes[17] / 2;
    int E6 = in_sizes[18] / 2;
    int E7 = in_sizes[19] / 2;
    int E8 = in_sizes[20] / 2;
    int E9 = in_sizes[21] / 2;

    // ---- sortA: p0,p1  /  sortB: p5,p6,p8,p9 ----
    int cb0 = 0, cb1 = N_SP, cb5 = cb1 + N_PMT, cb6 = cb5 + N_SP, cb8 = cb6 + N_HIT, cb9 = cb8 + N_PMT;
    int Ctot = cb9 + N_OPH;
    int CsplitA = cb5;                 // 80000

    SortCfg cfgA, cfgB;
    cfgA.src[0] = e_hit_sp;  cfgA.dst[0] = e_hit_sp + E0;  cfgA.cbase[0] = cb0;
    cfgA.src[1] = e_oph_pmt; cfgA.dst[1] = e_oph_pmt + E1; cfgA.cbase[1] = cb1;
    cfgA.ebase[0] = 0; cfgA.ebase[1] = E0; cfgA.ebase[2] = E0 + E1;
    cfgA.ebase[3] = cfgA.ebase[4] = 0x7fffffff;
    int EtotA = E0 + E1;

    cfgB.src[0] = e_evt_sp;  cfgB.dst[0] = e_evt_sp + E5;  cfgB.cbase[0] = cb5;
    cfgB.src[1] = e_sp_hit;  cfgB.dst[1] = e_sp_hit + E6;  cfgB.cbase[1] = cb6;
    cfgB.src[2] = e_opf_pmt; cfgB.dst[2] = e_opf_pmt + E8; cfgB.cbase[2] = cb8;
    cfgB.src[3] = e_pmt_oph; cfgB.dst[3] = e_pmt_oph + E9; cfgB.cbase[3] = cb9;
    cfgB.ebase[0] = 0; cfgB.ebase[1] = E5; cfgB.ebase[2] = E5 + E6;
    cfgB.ebase[3] = E5 + E6 + E8; cfgB.ebase[4] = E5 + E6 + E8 + E9;
    int EtotB = cfgB.ebase[4];

    int nbA = (CsplitA + SCHUNK - 1) / SCHUNK;          // 10
    int nbB = (Ctot - CsplitA + SCHUNK - 1) / SCHUNK;   // 71
    int* pbsA = pbs;
    int* pbsB = pbs + 16;

    const int db0 = 0, db1 = 300000, db5 = 500000, db6 = 501000, db8 = 551000, db9 = 553000;

    auto fused = [&](int i, const float* xs, const float* xt, int n_tgt,
                     int cb, int db, float* o, cudaStream_t st) {
        int fg = (n_tgt + NWARP * NT - 1) / (NWARP * NT); if (fg > 304) fg = 304;
        fused_pass<<<fg, 128, SMEM, st>>>(xs, xt, n_tgt, pssrc, poffs + cb, pcnt + cb,
                                          pdotj + db, ew + (size_t)i * 128, eb + i,
                                          w1 + (size_t)i * 8192, b1 + (size_t)i * 64,
                                          w2 + (size_t)i * 4096, b2 + (size_t)i * 64, o);
    };

    auto small = [&](int i, const float* xs, const float* xt, const int* e, int E,
                     int n_tgt, float* o, int accf, float* accbuf, cudaStream_t st) {
        int grid = (E + 15) / 16;
        edge_pass<<<grid, 512, 0, st>>>(xs, xt, e, e + E, E, ew + (size_t)i * 128, eb + i, accbuf);
        int ng = (n_tgt + NWARP * NT - 1) / (NWARP * NT); if (ng > 304) ng = 304;
        node_pass<<<ng, 128, SMEM, st>>>(xt, n_tgt, w1 + (size_t)i * 8192, b1 + (size_t)i * 64,
                                         w2 + (size_t)i * 4096, b2 + (size_t)i * 64,
                                         o, accf, accbuf);
    };

    // ==== fork: s1 (dotj), s2 (sortB) from root ====
    cudaEventRecord(evRoot, s0);
    cudaStreamWaitEvent(s1, evRoot, 0);
    cudaStreamWaitEvent(s2, evRoot, 0);

    // s0: sortA (critical path for phase 2)
    zero_k     <<<160, 256, 0, s0>>>(pcnt, CsplitA);
    hist_all   <<<(EtotA + 255) / 256, 256, 0, s0>>>(cfgA, EtotA, pcnt);
    scan1_k    <<<nbA, 256, 0, s0>>>(pcnt, 0, CsplitA, pbsA);
    scan2_k    <<<1, 128, 0, s0>>>(pbsA, nbA, 0);
    scan3_k    <<<nbA, 256, 0, s0>>>(pcnt, pbsA, 0, CsplitA, poffs, pcur);
    scatter_all<<<(EtotA + 255) / 256, 256, 0, s0>>>(cfgA, EtotA, pcur, pssrc);
    cudaEventRecord(evSA, s0);

    // s1: dotj for p0/p1 (independent of sorts)
    dotj_k<<<(N_HIT + 7) / 8, 256, 0, s1>>>(x_hit, N_HIT, ew + 0 * 128, pdotj + db0);
    dotj_k<<<(N_OPH + 7) / 8, 256, 0, s1>>>(x_oph, N_OPH, ew + 1 * 128, pdotj + db1);
    cudaEventRecord(evB, s1);

    // s2: sortB (needed only before phase 4) — overlaps phase-2 compute.
    // scan2 base = EtotA makes cur/offs ABSOLUTE into g_ssrc; scatter writes absolute (pssrc).
    zero_k     <<<296, 256, 0, s2>>>(pcnt + CsplitA, Ctot - CsplitA);
    hist_all   <<<(EtotB + 255) / 256, 256, 0, s2>>>(cfgB, EtotB, pcnt);
    scan1_k    <<<nbB, 256, 0, s2>>>(pcnt, CsplitA, Ctot, pbsB);
    scan2_k    <<<1, 128, 0, s2>>>(pbsB, nbB, EtotA);
    scan3_k    <<<nbB, 256, 0, s2>>>(pcnt, pbsB, CsplitA, Ctot, poffs, pcur);
    scatter_all<<<(EtotB + 255) / 256, 256, 0, s2>>>(cfgB, EtotB, pcur, pssrc);
    cudaEventRecord(evSB, s2);

    // ==== Phase 2: {p0,p3} on s0  ∥  {p1,p2} on s1 ====
    cudaStreamWaitEvent(s0, evB, 0);       // s0 needs dotj0
    cudaStreamWaitEvent(s1, evSA, 0);      // s1 needs sortA (p1 segment)

    fused(0, x_hit, x_sp, N_SP, cb0, db0, pn, s0);                          // plane_to_nexus
    small(3, pn, x_evt, e_sp_evt, E3, N_EVT, d_i, 0, acc_evt, s0);          // nexus_to_interaction

    fused(1, x_oph, x_pmt, N_PMT, cb1, db1, ppmt, s1);                      // hit_to_pmt
    small(2, ppmt, x_opf, e_pmt_opf, E2, N_OPF, popf, 0, acc_opf, s1);      // pmt_to_flash
    cudaEventRecord(evD, s1);

    // ==== Phase 3: p4 (needs popf + d_i) on s0 ====
    cudaStreamWaitEvent(s0, evD, 0);
    small(4, popf, x_evt, e_opf_evt, E4, N_EVT, d_i, 1, acc_evt, s0);       // flash_to_interaction

    // ==== Phase 4: {dotj5,p5,dotj6,p6} on s0 ∥ {p7,dotj8,p8,dotj9,p9} on s1 ====
    cudaEventRecord(evE, s0);
    cudaStreamWaitEvent(s1, evE, 0);
    cudaStreamWaitEvent(s0, evSB, 0);
    cudaStreamWaitEvent(s1, evSB, 0);

    dotj_k<<<(N_EVT + 7) / 8, 256, 0, s0>>>(d_i, N_EVT, ew + 5 * 128, pdotj + db5);
    fused(5, d_i, pn, N_SP, cb5, db5, d_n, s0);                             // interaction_to_nexus
    dotj_k<<<(N_SP + 7) / 8, 256, 0, s0>>>(d_n, N_SP, ew + 6 * 128, pdotj + db6);
    fused(6, d_n, x_hit, N_HIT, cb6, db6, d_p, s0);                         // nexus_to_plane

    small(7, d_i, popf, e_evt_opf, E7, N_OPF, d_opf, 0, acc_opf, s1);       // interaction_to_flash
    dotj_k<<<(N_OPF + 7) / 8, 256, 0, s1>>>(d_opf, N_OPF, ew + 8 * 128, pdotj + db8);
    fused(8, d_opf, ppmt, N_PMT, cb8, db8, d_pmt, s1);                      // flash_to_pmt
    dotj_k<<<(N_PMT + 7) / 8, 256, 0, s1>>>(d_pmt, N_PMT, ew + 9 * 128, pdotj + db9);
    fused(9, d_pmt, x_oph, N_OPH, cb9, db9, d_oph, s1);                     // pmt_to_ophit

    cudaEventRecord(evF, s1);
    cudaStreamWaitEvent(s0, evF, 0);
}

// round 9
// speedup vs baseline: 1.1017x; 1.1017x over previous
#include <cuda_runtime.h>

#define F 64
#define NT 4
#define NWARP 8            // 256-thread blocks

// Node counts (fixed by the problem)
#define N_HIT 300000
#define N_SP   50000
#define N_OPH 200000
#define N_PMT  30000
#define N_OPF   2000
#define N_EVT    256

#define CTOT 660000
#define ETOT 1510000
#define DTOT 600000

// ---- scratch (device globals) ----
__device__ float g_acc[(size_t)(N_OPF + N_EVT) * 128];
__device__ float g_nbuf[(size_t)N_SP * F];
__device__ float g_pmtbuf[(size_t)N_PMT * F];
__device__ float g_opfbuf[(size_t)N_OPF * F];
__device__ int   g_count[CTOT];
__device__ int   g_offs[CTOT];
__device__ int   g_cursor[CTOT];
__device__ int   g_ssrc[ETOT];
__device__ int   g_bsums[128];
__device__ float g_dotj[DTOT];

__device__ __forceinline__ float2 ffma2(float2 a, float2 b, float2 c) {
    unsigned long long ua = *reinterpret_cast<unsigned long long*>(&a);
    unsigned long long ub = *reinterpret_cast<unsigned long long*>(&b);
    unsigned long long uc = *reinterpret_cast<unsigned long long*>(&c);
    unsigned long long ud;
    asm("fma.rn.f32x2 %0, %1, %2, %3;" : "=l"(ud) : "l"(ua), "l"(ub), "l"(uc));
    return *reinterpret_cast<float2*>(&ud);
}

__device__ __forceinline__ float mishf(float x) {
    float e = __expf(fminf(x, 30.f));
    float t = e * (e + 2.f);
    return x * __fdividef(t, t + 2.f);
}

// ======================= batched sort machinery =======================

struct SortCfg {
    const int* src[4];
    const int* dst[4];
    int ebase[5];   // relative edge prefix (0-based within this sort job)
    int cbase[4];   // absolute target-count bases
};

__global__ void zero_k(int* __restrict__ p, int n) {
    int i = blockIdx.x * blockDim.x + threadIdx.x;
    for (; i < n; i += gridDim.x * blockDim.x) p[i] = 0;
}

__global__ void hist_all(SortCfg cfg, int Etot, int* __restrict__ cnt) {
    int i = blockIdx.x * blockDim.x + threadIdx.x;
    if (i >= Etot) return;
    int s = 0;
    while (i >= cfg.ebase[s + 1]) s++;
    int li = i - cfg.ebase[s];
    atomicAdd(&cnt[cfg.cbase[s] + cfg.dst[s][li]], 1);
}

#define SCHUNK 8192
// processes cnt[cbeg : cend), one block per SCHUNK chunk
__global__ void scan1_k(const int* __restrict__ cnt, int cbeg, int cend, int* __restrict__ bsums) {
    __shared__ int ts[256];
    int tid = threadIdx.x;
    int base = cbeg + blockIdx.x * SCHUNK;
    int s = 0;
#pragma unroll
    for (int j = 0; j < 32; j++) {
        int i = base + j * 256 + tid;
        if (i < cend) s += cnt[i];
    }
    ts[tid] = s; __syncthreads();
    for (int o = 128; o; o >>= 1) { if (tid < o) ts[tid] += ts[tid + o]; __syncthreads(); }
    if (!tid) bsums[blockIdx.x] = ts[0];
}

__global__ void scan2_k(int* __restrict__ bsums, int nb, int base) {
    __shared__ int sb[128];
    int tid = threadIdx.x;
    if (tid < nb) sb[tid] = bsums[tid];
    __syncthreads();
    if (tid == 0) {
        int run = base;
        for (int b = 0; b < nb; b++) { int t = sb[b]; sb[b] = run; run += t; }
    }
    __syncthreads();
    if (tid < nb) bsums[tid] = sb[tid];
}

__global__ void scan3_k(const int* __restrict__ cnt, const int* __restrict__ bsums,
                        int cbeg, int cend, int* __restrict__ offs, int* __restrict__ cur) {
    __shared__ int ts[256];
    int tid = threadIdx.x;
    int base = cbeg + blockIdx.x * SCHUNK + tid * 32;
    int v[32]; int s = 0;
#pragma unroll
    for (int j = 0; j < 32; j++) {
        int i = base + j;
        v[j] = (i < cend) ? cnt[i] : 0;
        s += v[j];
    }
    ts[tid] = s; __syncthreads();
    for (int off = 1; off < 256; off <<= 1) {
        int add = (tid >= off) ? ts[tid - off] : 0;
        __syncthreads();
        ts[tid] += add;
        __syncthreads();
    }
    int run = (tid ? ts[tid - 1] : 0) + bsums[blockIdx.x];
#pragma unroll
    for (int j = 0; j < 32; j++) {
        int i = base + j;
        if (i < cend) { offs[i] = run; cur[i] = run; run += v[j]; }
    }
}

// cur holds ABSOLUTE positions into ssrc; writes are absolute.
__global__ void scatter_all(SortCfg cfg, int Etot, int* __restrict__ cur, int* __restrict__ ssrc) {
    int i = blockIdx.x * blockDim.x + threadIdx.x;
    if (i >= Etot) return;
    int s = 0;
    while (i >= cfg.ebase[s + 1]) s++;
    int li = i - cfg.ebase[s];
    int pos = atomicAdd(&cur[cfg.cbase[s] + cfg.dst[s][li]], 1);
    ssrc[pos] = cfg.src[s][li];
}

__global__ void dotj_k(const float* __restrict__ xsrc, int n_src,
                       const float* __restrict__ eW, float* __restrict__ dotj) {
    int lane = threadIdx.x & 31;
    int node = (blockIdx.x * blockDim.x + threadIdx.x) >> 5;
    float wj0 = eW[64 + 2 * lane], wj1 = eW[65 + 2 * lane];
    if (node >= n_src) return;
    float2 x = *reinterpret_cast<const float2*>(xsrc + (size_t)node * F + 2 * lane);
    float p = x.x * wj0 + x.y * wj1;
#pragma unroll
    for (int o = 16; o; o >>= 1) p += __shfl_xor_sync(0xffffffffu, p, o);
    if (!lane) dotj[node] = p;
}

// ======================= shared MLP helpers =======================
// smem floats: [0:8192) w1 packed, [8192:12288) w2 packed, [12288:12352) b1,
// [12352:12416) b2, [12416:...) cat buffers (NWARP * NT * 128 float2 = 32KB)

__device__ __forceinline__ void load_weights(float* sm, const float* __restrict__ w1,
                                             const float* __restrict__ b1,
                                             const float* __restrict__ w2,
                                             const float* __restrict__ b2, int tid) {
    float4* w1p = reinterpret_cast<float4*>(sm);
    float4* w2p = reinterpret_cast<float4*>(sm + 8192);
    for (int e = tid; e < 2048; e += 256) {
        int kk = e >> 5, l = e & 31;
        float2 a = *reinterpret_cast<const float2*>(w1 + (2 * kk) * 64 + 2 * l);
        float2 b = *reinterpret_cast<const float2*>(w1 + (2 * kk + 1) * 64 + 2 * l);
        w1p[e] = make_float4(a.x, a.y, b.x, b.y);
    }
    for (int e = tid; e < 1024; e += 256) {
        int kk = e >> 5, l = e & 31;
        float2 a = *reinterpret_cast<const float2*>(w2 + (2 * kk) * 64 + 2 * l);
        float2 b = *reinterpret_cast<const float2*>(w2 + (2 * kk + 1) * 64 + 2 * l);
        w2p[e] = make_float4(a.x, a.y, b.x, b.y);
    }
    if (tid < 64) { sm[12288 + tid] = b1[tid]; sm[12352 + tid] = b2[tid]; }
}

__device__ __forceinline__ void mlp_apply(const float* sm, float2* cw, int lane, float2 o[NT]) {
    const float4* w1p = reinterpret_cast<const float4*>(sm);
    const float4* w2p = reinterpret_cast<const float4*>(sm + 8192);
    float2 acc[NT];
    float2 bv1 = *reinterpret_cast<const float2*>(sm + 12288 + 2 * lane);
#pragma unroll
    for (int t = 0; t < NT; t++) acc[t] = bv1;
#pragma unroll 4
    for (int kk = 0; kk < 64; kk++) {
        float4 wv = w1p[kk * 32 + lane];
#pragma unroll
        for (int t = 0; t < NT; t++) {
            float4 cv = *reinterpret_cast<const float4*>(cw + t * 128 + 2 * kk);
            acc[t] = ffma2(make_float2(wv.x, wv.y), make_float2(cv.x, cv.y), acc[t]);
            acc[t] = ffma2(make_float2(wv.z, wv.w), make_float2(cv.z, cv.w), acc[t]);
        }
    }
    __syncwarp();
#pragma unroll
    for (int t = 0; t < NT; t++) {
        float h0 = mishf(acc[t].x), h1 = mishf(acc[t].y);
        cw[t * 128 + 2 * lane]     = make_float2(h0, h0);
        cw[t * 128 + 2 * lane + 1] = make_float2(h1, h1);
    }
    __syncwarp();
    float2 bv2 = *reinterpret_cast<const float2*>(sm + 12352 + 2 * lane);
#pragma unroll
    for (int t = 0; t < NT; t++) acc[t] = bv2;
#pragma unroll 4
    for (int kk = 0; kk < 32; kk++) {
        float4 wv = w2p[kk * 32 + lane];
#pragma unroll
        for (int t = 0; t < NT; t++) {
            float4 cv = *reinterpret_cast<const float4*>(cw + t * 128 + 2 * kk);
            acc[t] = ffma2(make_float2(wv.x, wv.y), make_float2(cv.x, cv.y), acc[t]);
            acc[t] = ffma2(make_float2(wv.z, wv.w), make_float2(cv.z, cv.w), acc[t]);
        }
    }
#pragma unroll
    for (int t = 0; t < NT; t++) o[t] = make_float2(mishf(acc[t].x), mishf(acc[t].y));
}

// ======================= fused segment-reduce + MLP =======================
__global__ void __launch_bounds__(256, 2) fused_pass(
    const float* __restrict__ xsrc, const float* __restrict__ xtgt, int n_tgt,
    const int* __restrict__ ssrc, const int* __restrict__ offs, const int* __restrict__ cnt,
    const float* __restrict__ dotj,
    const float* __restrict__ eW, const float* __restrict__ eB,
    const float* __restrict__ w1, const float* __restrict__ b1,
    const float* __restrict__ w2, const float* __restrict__ b2,
    float* __restrict__ out) {
    extern __shared__ float sm[];
    float2* cats = reinterpret_cast<float2*>(sm + 12416);

    int tid = threadIdx.x;
    load_weights(sm, w1, b1, w2, b2, tid);
    __syncthreads();

    int warp = tid >> 5, lane = tid & 31;
    float wi0 = eW[2 * lane], wi1 = eW[2 * lane + 1];
    float bia = eB[0];
    float2* cw = cats + warp * NT * 128;
    int stride = gridDim.x * NWARP * NT;

    for (int base = (blockIdx.x * NWARP + warp) * NT; base < n_tgt; base += stride) {
        int nv = n_tgt - base; if (nv > NT) nv = NT;

        int o[NT], c[NT];
        float2 xiv[NT];
        float dot_i[NT];
#pragma unroll
        for (int t = 0; t < NT; t++) {
            bool v = (t < nv);
            size_t node = (size_t)(base + t);
            o[t] = v ? offs[node] : 0;
            c[t] = v ? cnt[node]  : 0;
            xiv[t] = v ? *reinterpret_cast<const float2*>(xtgt + node * F + 2 * lane)
                       : make_float2(0.f, 0.f);
            float p = xiv[t].x * wi0 + xiv[t].y * wi1;
#pragma unroll
            for (int off = 16; off; off >>= 1) p += __shfl_xor_sync(0xffffffffu, p, off);
            dot_i[t] = p + bia;
        }

        int maxc = c[0];
#pragma unroll
        for (int t = 1; t < NT; t++) maxc = max(maxc, c[t]);

        float den0[NT], num0[NT], den1[NT], num1[NT];
#pragma unroll
        for (int t = 0; t < NT; t++) { den0[t] = 0.f; num0[t] = 0.f; den1[t] = 0.f; num1[t] = 0.f; }

        for (int k = 0; k < maxc; k++) {
            float  djv[NT];
            float2 xjv[NT];
#pragma unroll
            for (int t = 0; t < NT; t++) {
                if (k < c[t]) {
                    int s = ssrc[o[t] + k];
                    djv[t] = dotj[s];
                    xjv[t] = *reinterpret_cast<const float2*>(xsrc + (size_t)s * F + 2 * lane);
                }
            }
#pragma unroll
            for (int t = 0; t < NT; t++) {
                if (k < c[t]) {
                    float z = dot_i[t] + djv[t];
                    float w = __fdividef(1.f, 1.f + __expf(-z));
                    float m0 = w * xjv[t].x, m1 = w * xjv[t].y;
                    float e0 = __expf(m0),   e1 = __expf(m1);
                    den0[t] += e0; num0[t] += e0 * m0;
                    den1[t] += e1; num1[t] += e1 * m1;
                }
            }
        }

#pragma unroll
        for (int t = 0; t < NT; t++) {
            float a0 = __fdividef(num0[t], den0[t] + 1e-16f);
            float a1 = __fdividef(num1[t], den1[t] + 1e-16f);
            cw[t * 128 + 2 * lane]          = make_float2(a0, a0);
            cw[t * 128 + 2 * lane + 1]      = make_float2(a1, a1);
            cw[t * 128 + 64 + 2 * lane]     = make_float2(xiv[t].x, xiv[t].x);
            cw[t * 128 + 64 + 2 * lane + 1] = make_float2(xiv[t].y, xiv[t].y);
        }
        __syncwarp();

        float2 ov[NT];
        mlp_apply(sm, cw, lane, ov);

#pragma unroll
        for (int t = 0; t < NT; t++) {
            if (t < nv) {
                *reinterpret_cast<float2*>(out + (size_t)(base + t) * F + 2 * lane) = ov[t];
            }
        }
        __syncwarp();
    }
}

// ======================= small-pass atomic path =======================

__global__ void edge_pass(const float* __restrict__ xsrc, const float* __restrict__ xtgt,
                          const int* __restrict__ src, const int* __restrict__ dst, int E,
                          const float* __restrict__ eW, const float* __restrict__ eB,
                          float* __restrict__ acc) {
    __shared__ float Ws[2 * F];
    __shared__ float Bs;
    int tid = threadIdx.x;
    if (tid < 2 * F) Ws[tid] = eW[tid];
    if (tid == 0) Bs = eB[0];
    __syncthreads();

    int lane = tid & 31;
    int e = blockIdx.x * (blockDim.x >> 5) + (tid >> 5);
    if (e >= E) return;

    int s = src[e], d = dst[e];
    float2 xj = *reinterpret_cast<const float2*>(xsrc + (size_t)s * F + 2 * lane);
    float2 xi = *reinterpret_cast<const float2*>(xtgt + (size_t)d * F + 2 * lane);

    float part = xi.x * Ws[2 * lane] + xi.y * Ws[2 * lane + 1]
               + xj.x * Ws[F + 2 * lane] + xj.y * Ws[F + 2 * lane + 1];
#pragma unroll
    for (int o = 16; o; o >>= 1) part += __shfl_xor_sync(0xffffffffu, part, o);

    float w = __fdividef(1.f, 1.f + __expf(-(part + Bs)));
    float m0 = w * xj.x, m1 = w * xj.y;
    float e0 = __expf(m0), e1 = __expf(m1);

    float4 v = make_float4(e0, e0 * m0, e1, e1 * m1);
    atomicAdd(reinterpret_cast<float4*>(acc + (size_t)d * 128 + 4 * lane), v);
}

__global__ void __launch_bounds__(256, 2) node_pass(
    const float* __restrict__ xtgt, int n_tgt,
    const float* __restrict__ w1, const float* __restrict__ b1,
    const float* __restrict__ w2, const float* __restrict__ b2,
    float* __restrict__ out, int accumulate, float* __restrict__ accbuf) {
    extern __shared__ float sm[];
    float2* cats = reinterpret_cast<float2*>(sm + 12416);

    int tid = threadIdx.x;
    load_weights(sm, w1, b1, w2, b2, tid);
    __syncthreads();

    int warp = tid >> 5, lane = tid & 31;
    float2* cw = cats + warp * NT * 128;
    int stride = gridDim.x * NWARP * NT;

    for (int base = (blockIdx.x * NWARP + warp) * NT; base < n_tgt; base += stride) {
        int nv = n_tgt - base; if (nv > NT) nv = NT;

#pragma unroll
        for (int t = 0; t < NT; t++) {
            if (t < nv) {
                size_t node = (size_t)(base + t);
                float4* ap = reinterpret_cast<float4*>(accbuf + node * 128 + 4 * lane);
                float4 a = *ap;
                *ap = make_float4(0.f, 0.f, 0.f, 0.f);  // self-clean for replay
                float2 xt = *reinterpret_cast<const float2*>(xtgt + node * F + 2 * lane);
                float a0 = __fdividef(a.y, a.x + 1e-16f);
                float a1 = __fdividef(a.w, a.z + 1e-16f);
                cw[t * 128 + 2 * lane]          = make_float2(a0, a0);
                cw[t * 128 + 2 * lane + 1]      = make_float2(a1, a1);
                cw[t * 128 + 64 + 2 * lane]     = make_float2(xt.x, xt.x);
                cw[t * 128 + 64 + 2 * lane + 1] = make_float2(xt.y, xt.y);
            }
        }
        __syncwarp();

        float2 ov[NT];
        mlp_apply(sm, cw, lane, ov);

#pragma unroll
        for (int t = 0; t < NT; t++) {
            if (t < nv) {
                float2* op = reinterpret_cast<float2*>(out + (size_t)(base + t) * F + 2 * lane);
                float2 o = ov[t];
                if (accumulate) { float2 pv = *op; o.x += pv.x; o.y += pv.y; }
                *op = o;
            }
        }
        __syncwarp();
    }
}

// ======================= launcher =======================

extern "C" void kernel_launch(void* const* d_in, const int* in_sizes, int n_in,
                              void* d_out, int out_size) {
    const float* x_hit = (const float*)d_in[0];
    const float* x_sp  = (const float*)d_in[1];
    const float* x_oph = (const float*)d_in[2];
    const float* x_pmt = (const float*)d_in[3];
    const float* x_opf = (const float*)d_in[4];
    const float* x_evt = (const float*)d_in[5];
    const float* ew = (const float*)d_in[6];
    const float* eb = (const float*)d_in[7];
    const float* w1 = (const float*)d_in[8];
    const float* b1 = (const float*)d_in[9];
    const float* w2 = (const float*)d_in[10];
    const float* b2 = (const float*)d_in[11];
    const int* e_hit_sp  = (const int*)d_in[12];
    const int* e_oph_pmt = (const int*)d_in[13];
    const int* e_pmt_opf = (const int*)d_in[14];
    const int* e_sp_evt  = (const int*)d_in[15];
    const int* e_opf_evt = (const int*)d_in[16];
    const int* e_evt_sp  = (const int*)d_in[17];
    const int* e_sp_hit  = (const int*)d_in[18];
    const int* e_evt_opf = (const int*)d_in[19];
    const int* e_opf_pmt = (const int*)d_in[20];
    const int* e_pmt_oph = (const int*)d_in[21];

    float* out = (float*)d_out;
    float* d_p   = out;
    float* d_n   = d_p   + (size_t)N_HIT * F;
    float* d_oph = d_n   + (size_t)N_SP  * F;
    float* d_pmt = d_oph + (size_t)N_OPH * F;
    float* d_opf = d_pmt + (size_t)N_PMT * F;
    float* d_i   = d_opf + (size_t)N_OPF * F;

    float *pacc, *pn, *ppmt, *popf, *pdotj;
    int *pcnt, *poffs, *pcur, *pssrc, *pbs;
    cudaGetSymbolAddress((void**)&pacc,  g_acc);
    cudaGetSymbolAddress((void**)&pn,    g_nbuf);
    cudaGetSymbolAddress((void**)&ppmt,  g_pmtbuf);
    cudaGetSymbolAddress((void**)&popf,  g_opfbuf);
    cudaGetSymbolAddress((void**)&pdotj, g_dotj);
    cudaGetSymbolAddress((void**)&pcnt,  g_count);
    cudaGetSymbolAddress((void**)&poffs, g_offs);
    cudaGetSymbolAddress((void**)&pcur,  g_cursor);
    cudaGetSymbolAddress((void**)&pssrc, g_ssrc);
    cudaGetSymbolAddress((void**)&pbs,   g_bsums);

    float* acc_opf = pacc;                          // p2, p7
    float* acc_evt = pacc + (size_t)N_OPF * 128;    // p3, p4

    const int SMEM = 82432;  // 12416 floats + NWARP*NT*128 float2 (32KB)
    cudaFuncSetAttribute(node_pass,  cudaFuncAttributeMaxDynamicSharedMemorySize, SMEM);
    cudaFuncSetAttribute(fused_pass, cudaFuncAttributeMaxDynamicSharedMemorySize, SMEM);

    static cudaStream_t s1 = nullptr, s2 = nullptr;
    static cudaEvent_t evRoot = nullptr, evSA = nullptr, evB = nullptr, evD = nullptr,
                       evE = nullptr, evSB = nullptr, evF = nullptr;
    if (!s1) {
        cudaStreamCreateWithFlags(&s1, cudaStreamNonBlocking);
        cudaStreamCreateWithFlags(&s2, cudaStreamNonBlocking);
        cudaEventCreateWithFlags(&evRoot, cudaEventDisableTiming);
        cudaEventCreateWithFlags(&evSA, cudaEventDisableTiming);
        cudaEventCreateWithFlags(&evB, cudaEventDisableTiming);
        cudaEventCreateWithFlags(&evD, cudaEventDisableTiming);
        cudaEventCreateWithFlags(&evE, cudaEventDisableTiming);
        cudaEventCreateWithFlags(&evSB, cudaEventDisableTiming);
        cudaEventCreateWithFlags(&evF, cudaEventDisableTiming);
    }
    cudaStream_t s0 = 0;

    int E0 = in_sizes[12] / 2;
    int E1 = in_sizes[13] / 2;
    int E2 = in_sizes[14] / 2;
    int E3 = in_sizes[15] / 2;
    int E4 = in_sizes[16] / 2;
    int E5 = in_sizes[17] / 2;
    int E6 = in_sizes[18] / 2;
    int E7 = in_sizes[19] / 2;
    int E8 = in_sizes[20] / 2;
    int E9 = in_sizes[21] / 2;

    // ---- sortA: p0,p1  /  sortB: p5,p6,p8,p9 ----
    int cb0 = 0, cb1 = N_SP, cb5 = cb1 + N_PMT, cb6 = cb5 + N_SP, cb8 = cb6 + N_HIT, cb9 = cb8 + N_PMT;
    int Ctot = cb9 + N_OPH;
    int CsplitA = cb5;                 // 80000

    SortCfg cfgA, cfgB;
    cfgA.src[0] = e_hit_sp;  cfgA.dst[0] = e_hit_sp + E0;  cfgA.cbase[0] = cb0;
    cfgA.src[1] = e_oph_pmt; cfgA.dst[1] = e_oph_pmt + E1; cfgA.cbase[1] = cb1;
    cfgA.ebase[0] = 0; cfgA.ebase[1] = E0; cfgA.ebase[2] = E0 + E1;
    cfgA.ebase[3] = cfgA.ebase[4] = 0x7fffffff;
    int EtotA = E0 + E1;

    cfgB.src[0] = e_evt_sp;  cfgB.dst[0] = e_evt_sp + E5;  cfgB.cbase[0] = cb5;
    cfgB.src[1] = e_sp_hit;  cfgB.dst[1] = e_sp_hit + E6;  cfgB.cbase[1] = cb6;
    cfgB.src[2] = e_opf_pmt; cfgB.dst[2] = e_opf_pmt + E8; cfgB.cbase[2] = cb8;
    cfgB.src[3] = e_pmt_oph; cfgB.dst[3] = e_pmt_oph + E9; cfgB.cbase[3] = cb9;
    cfgB.ebase[0] = 0; cfgB.ebase[1] = E5; cfgB.ebase[2] = E5 + E6;
    cfgB.ebase[3] = E5 + E6 + E8; cfgB.ebase[4] = E5 + E6 + E8 + E9;
    int EtotB = cfgB.ebase[4];

    int nbA = (CsplitA + SCHUNK - 1) / SCHUNK;          // 10
    int nbB = (Ctot - CsplitA + SCHUNK - 1) / SCHUNK;   // 71
    int* pbsA = pbs;
    int* pbsB = pbs + 16;

    const int db0 = 0, db1 = 300000, db5 = 500000, db6 = 501000, db8 = 551000, db9 = 553000;

    auto fused = [&](int i, const float* xs, const float* xt, int n_tgt,
                     int cb, int db, float* o, cudaStream_t st) {
        int fg = (n_tgt + NWARP * NT - 1) / (NWARP * NT); if (fg > 296) fg = 296;
        fused_pass<<<fg, 256, SMEM, st>>>(xs, xt, n_tgt, pssrc, poffs + cb, pcnt + cb,
                                          pdotj + db, ew + (size_t)i * 128, eb + i,
                                          w1 + (size_t)i * 8192, b1 + (size_t)i * 64,
                                          w2 + (size_t)i * 4096, b2 + (size_t)i * 64, o);
    };

    auto small = [&](int i, const float* xs, const float* xt, const int* e, int E,
                     int n_tgt, float* o, int accf, float* accbuf, cudaStream_t st) {
        int grid = (E + 15) / 16;
        edge_pass<<<grid, 512, 0, st>>>(xs, xt, e, e + E, E, ew + (size_t)i * 128, eb + i, accbuf);
        int ng = (n_tgt + NWARP * NT - 1) / (NWARP * NT); if (ng > 296) ng = 296;
        node_pass<<<ng, 256, SMEM, st>>>(xt, n_tgt, w1 + (size_t)i * 8192, b1 + (size_t)i * 64,
                                         w2 + (size_t)i * 4096, b2 + (size_t)i * 64,
                                         o, accf, accbuf);
    };

    // ==== fork: s1 (dotj), s2 (sortB) from root ====
    cudaEventRecord(evRoot, s0);
    cudaStreamWaitEvent(s1, evRoot, 0);
    cudaStreamWaitEvent(s2, evRoot, 0);

    // s0: sortA (critical path for phase 2)
    zero_k     <<<160, 256, 0, s0>>>(pcnt, CsplitA);
    hist_all   <<<(EtotA + 255) / 256, 256, 0, s0>>>(cfgA, EtotA, pcnt);
    scan1_k    <<<nbA, 256, 0, s0>>>(pcnt, 0, CsplitA, pbsA);
    scan2_k    <<<1, 128, 0, s0>>>(pbsA, nbA, 0);
    scan3_k    <<<nbA, 256, 0, s0>>>(pcnt, pbsA, 0, CsplitA, poffs, pcur);
    scatter_all<<<(EtotA + 255) / 256, 256, 0, s0>>>(cfgA, EtotA, pcur, pssrc);
    cudaEventRecord(evSA, s0);

    // s1: dotj for p0/p1 (independent of sorts)
    dotj_k<<<(N_HIT + 7) / 8, 256, 0, s1>>>(x_hit, N_HIT, ew + 0 * 128, pdotj + db0);
    dotj_k<<<(N_OPH + 7) / 8, 256, 0, s1>>>(x_oph, N_OPH, ew + 1 * 128, pdotj + db1);
    cudaEventRecord(evB, s1);

    // s2: sortB (needed only before phase 4) — overlaps phase-2 compute.
    // scan2 base = EtotA makes cur/offs ABSOLUTE into g_ssrc; scatter writes absolute (pssrc).
    zero_k     <<<296, 256, 0, s2>>>(pcnt + CsplitA, Ctot - CsplitA);
    hist_all   <<<(EtotB + 255) / 256, 256, 0, s2>>>(cfgB, EtotB, pcnt);
    scan1_k    <<<nbB, 256, 0, s2>>>(pcnt, CsplitA, Ctot, pbsB);
    scan2_k    <<<1, 128, 0, s2>>>(pbsB, nbB, EtotA);
    scan3_k    <<<nbB, 256, 0, s2>>>(pcnt, pbsB, CsplitA, Ctot, poffs, pcur);
    scatter_all<<<(EtotB + 255) / 256, 256, 0, s2>>>(cfgB, EtotB, pcur, pssrc);
    cudaEventRecord(evSB, s2);

    // ==== Phase 2: {p0,p3} on s0  ∥  {p1,p2} on s1 ====
    cudaStreamWaitEvent(s0, evB, 0);       // s0 needs dotj0
    cudaStreamWaitEvent(s1, evSA, 0);      // s1 needs sortA (p1 segment)

    fused(0, x_hit, x_sp, N_SP, cb0, db0, pn, s0);                          // plane_to_nexus
    small(3, pn, x_evt, e_sp_evt, E3, N_EVT, d_i, 0, acc_evt, s0);          // nexus_to_interaction

    fused(1, x_oph, x_pmt, N_PMT, cb1, db1, ppmt, s1);                      // hit_to_pmt
    small(2, ppmt, x_opf, e_pmt_opf, E2, N_OPF, popf, 0, acc_opf, s1);      // pmt_to_flash
    cudaEventRecord(evD, s1);

    // ==== Phase 3: p4 (needs popf + d_i) on s0 ====
    cudaStreamWaitEvent(s0, evD, 0);
    small(4, popf, x_evt, e_opf_evt, E4, N_EVT, d_i, 1, acc_evt, s0);       // flash_to_interaction

    // ==== Phase 4: {dotj5,p5,dotj6,p6} on s0 ∥ {p7,dotj8,p8,dotj9,p9} on s1 ====
    cudaEventRecord(evE, s0);
    cudaStreamWaitEvent(s1, evE, 0);
    cudaStreamWaitEvent(s0, evSB, 0);
    cudaStreamWaitEvent(s1, evSB, 0);

    dotj_k<<<(N_EVT + 7) / 8, 256, 0, s0>>>(d_i, N_EVT, ew + 5 * 128, pdotj + db5);
    fused(5, d_i, pn, N_SP, cb5, db5, d_n, s0);                             // interaction_to_nexus
    dotj_k<<<(N_SP + 7) / 8, 256, 0, s0>>>(d_n, N_SP, ew + 6 * 128, pdotj + db6);
    fused(6, d_n, x_hit, N_HIT, cb6, db6, d_p, s0);                         // nexus_to_plane

    small(7, d_i, popf, e_evt_opf, E7, N_OPF, d_opf, 0, acc_opf, s1);       // interaction_to_flash
    dotj_k<<<(N_OPF + 7) / 8, 256, 0, s1>>>(d_opf, N_OPF, ew + 8 * 128, pdotj + db8);
    fused(8, d_opf, ppmt, N_PMT, cb8, db8, d_pmt, s1);                      // flash_to_pmt
    dotj_k<<<(N_PMT + 7) / 8, 256, 0, s1>>>(d_pmt, N_PMT, ew + 9 * 128, pdotj + db9);
    fused(9, d_pmt, x_oph, N_OPH, cb9, db9, d_oph, s1);                     // pmt_to_ophit

    cudaEventRecord(evF, s1);
    cudaStreamWaitEvent(s0, evF, 0);
}

// round 10
// speedup vs baseline: 1.3514x; 1.2266x over previous
#include <cuda_runtime.h>

#define F 64
#define NT 8
#define NTH 4              // aggregation half-width
#define NWARP 8            // 256-thread blocks

// Node counts (fixed by the problem)
#define N_HIT 300000
#define N_SP   50000
#define N_OPH 200000
#define N_PMT  30000
#define N_OPF   2000
#define N_EVT    256

#define CTOT 660000
#define ETOT 1510000
#define DTOT 600000

// ---- scratch (device globals) ----
__device__ float g_acc[(size_t)(N_OPF + N_EVT) * 128];
__device__ float g_nbuf[(size_t)N_SP * F];
__device__ float g_pmtbuf[(size_t)N_PMT * F];
__device__ float g_opfbuf[(size_t)N_OPF * F];
__device__ int   g_count[CTOT];
__device__ int   g_offs[CTOT];
__device__ int   g_cursor[CTOT];
__device__ int   g_ssrc[ETOT];
__device__ int   g_bsums[128];
__device__ float g_dotj[DTOT];

__device__ __forceinline__ float2 ffma2(float2 a, float2 b, float2 c) {
    unsigned long long ua = *reinterpret_cast<unsigned long long*>(&a);
    unsigned long long ub = *reinterpret_cast<unsigned long long*>(&b);
    unsigned long long uc = *reinterpret_cast<unsigned long long*>(&c);
    unsigned long long ud;
    asm("fma.rn.f32x2 %0, %1, %2, %3;" : "=l"(ud) : "l"(ua), "l"(ub), "l"(uc));
    return *reinterpret_cast<float2*>(&ud);
}

__device__ __forceinline__ float mishf(float x) {
    float e = __expf(fminf(x, 30.f));
    float t = e * (e + 2.f);
    return x * __fdividef(t, t + 2.f);
}

// ======================= batched sort machinery =======================

struct SortCfg {
    const int* src[4];
    const int* dst[4];
    int ebase[5];
    int cbase[4];
};

__global__ void zero_k(int* __restrict__ p, int n) {
    int i = blockIdx.x * blockDim.x + threadIdx.x;
    for (; i < n; i += gridDim.x * blockDim.x) p[i] = 0;
}

__global__ void hist_all(SortCfg cfg, int Etot, int* __restrict__ cnt) {
    int i = blockIdx.x * blockDim.x + threadIdx.x;
    if (i >= Etot) return;
    int s = 0;
    while (i >= cfg.ebase[s + 1]) s++;
    int li = i - cfg.ebase[s];
    atomicAdd(&cnt[cfg.cbase[s] + cfg.dst[s][li]], 1);
}

#define SCHUNK 8192
__global__ void scan1_k(const int* __restrict__ cnt, int cbeg, int cend, int* __restrict__ bsums) {
    __shared__ int ts[256];
    int tid = threadIdx.x;
    int base = cbeg + blockIdx.x * SCHUNK;
    int s = 0;
#pragma unroll
    for (int j = 0; j < 32; j++) {
        int i = base + j * 256 + tid;
        if (i < cend) s += cnt[i];
    }
    ts[tid] = s; __syncthreads();
    for (int o = 128; o; o >>= 1) { if (tid < o) ts[tid] += ts[tid + o]; __syncthreads(); }
    if (!tid) bsums[blockIdx.x] = ts[0];
}

__global__ void scan2_k(int* __restrict__ bsums, int nb, int base) {
    __shared__ int sb[128];
    int tid = threadIdx.x;
    if (tid < nb) sb[tid] = bsums[tid];
    __syncthreads();
    if (tid == 0) {
        int run = base;
        for (int b = 0; b < nb; b++) { int t = sb[b]; sb[b] = run; run += t; }
    }
    __syncthreads();
    if (tid < nb) bsums[tid] = sb[tid];
}

__global__ void scan3_k(const int* __restrict__ cnt, const int* __restrict__ bsums,
                        int cbeg, int cend, int* __restrict__ offs, int* __restrict__ cur) {
    __shared__ int ts[256];
    int tid = threadIdx.x;
    int base = cbeg + blockIdx.x * SCHUNK + tid * 32;
    int v[32]; int s = 0;
#pragma unroll
    for (int j = 0; j < 32; j++) {
        int i = base + j;
        v[j] = (i < cend) ? cnt[i] : 0;
        s += v[j];
    }
    ts[tid] = s; __syncthreads();
    for (int off = 1; off < 256; off <<= 1) {
        int add = (tid >= off) ? ts[tid - off] : 0;
        __syncthreads();
        ts[tid] += add;
        __syncthreads();
    }
    int run = (tid ? ts[tid - 1] : 0) + bsums[blockIdx.x];
#pragma unroll
    for (int j = 0; j < 32; j++) {
        int i = base + j;
        if (i < cend) { offs[i] = run; cur[i] = run; run += v[j]; }
    }
}

// cur holds ABSOLUTE positions into ssrc; writes are absolute.
__global__ void scatter_all(SortCfg cfg, int Etot, int* __restrict__ cur, int* __restrict__ ssrc) {
    int i = blockIdx.x * blockDim.x + threadIdx.x;
    if (i >= Etot) return;
    int s = 0;
    while (i >= cfg.ebase[s + 1]) s++;
    int li = i - cfg.ebase[s];
    int pos = atomicAdd(&cur[cfg.cbase[s] + cfg.dst[s][li]], 1);
    ssrc[pos] = cfg.src[s][li];
}

__global__ void dotj_k(const float* __restrict__ xsrc, int n_src,
                       const float* __restrict__ eW, float* __restrict__ dotj) {
    int lane = threadIdx.x & 31;
    int node = (blockIdx.x * blockDim.x + threadIdx.x) >> 5;
    float wj0 = eW[64 + 2 * lane], wj1 = eW[65 + 2 * lane];
    if (node >= n_src) return;
    float2 x = *reinterpret_cast<const float2*>(xsrc + (size_t)node * F + 2 * lane);
    float p = x.x * wj0 + x.y * wj1;
#pragma unroll
    for (int o = 16; o; o >>= 1) p += __shfl_xor_sync(0xffffffffu, p, o);
    if (!lane) dotj[node] = p;
}

// ======================= shared MLP helpers (K-pair FFMA2 layout) =======================
// smem floats: [0:8192) w1 packed, [8192:12288) w2 packed, [12288:12352) b1,
// [12352:12416) b2, [12416:20608) cat buffers (NWARP * NT * 64 float2 = 32KB).
//
// Weight packing (per layer): entry e = kp*32 + lane is float4
//   ( w[2kp][2l], w[2kp+1][2l], w[2kp][2l+1], w[2kp+1][2l+1] )
// FFMA2 lanes span two consecutive k values; acc = (sum_even_k, sum_odd_k) per feature,
// folded by one FADD at layer end. Cat is stored UNduplicated: 128 floats/node.

__device__ __forceinline__ void load_weights(float* sm, const float* __restrict__ w1,
                                             const float* __restrict__ b1,
                                             const float* __restrict__ w2,
                                             const float* __restrict__ b2, int tid) {
    float4* w1p = reinterpret_cast<float4*>(sm);
    float4* w2p = reinterpret_cast<float4*>(sm + 8192);
    for (int e = tid; e < 2048; e += 256) {
        int kp = e >> 5, l = e & 31;
        const float* r0 = w1 + (size_t)(2 * kp) * 64 + 2 * l;
        const float* r1 = r0 + 64;
        w1p[e] = make_float4(r0[0], r1[0], r0[1], r1[1]);
    }
    for (int e = tid; e < 1024; e += 256) {
        int kp = e >> 5, l = e & 31;
        const float* r0 = w2 + (size_t)(2 * kp) * 64 + 2 * l;
        const float* r1 = r0 + 64;
        w2p[e] = make_float4(r0[0], r1[0], r0[1], r1[1]);
    }
    if (tid < 64) { sm[12288 + tid] = b1[tid]; sm[12352 + tid] = b2[tid]; }
}

// cw: per-warp cat region, node t occupies cw[t*64 .. t*64+63] (float2), i.e. 32 float4.
__device__ __forceinline__ void mlp_apply(const float* sm, float2* cw, int lane, float2 o[NT]) {
    const float4* w1p = reinterpret_cast<const float4*>(sm);
    const float4* w2p = reinterpret_cast<const float4*>(sm + 8192);
    const float4* cw4 = reinterpret_cast<const float4*>(cw);
    float2 acc0[NT], acc1[NT];
    float b10 = sm[12288 + 2 * lane], b11 = sm[12288 + 2 * lane + 1];
#pragma unroll
    for (int t = 0; t < NT; t++) { acc0[t] = make_float2(b10, 0.f); acc1[t] = make_float2(b11, 0.f); }
#pragma unroll 2
    for (int q = 0; q < 32; q++) {              // 4 input features per iter
        float4 wa = w1p[(2 * q) * 32 + lane];
        float4 wb = w1p[(2 * q + 1) * 32 + lane];
#pragma unroll
        for (int t = 0; t < NT; t++) {
            float4 cv = cw4[t * 32 + q];
            acc0[t] = ffma2(make_float2(wa.x, wa.y), make_float2(cv.x, cv.y), acc0[t]);
            acc1[t] = ffma2(make_float2(wa.z, wa.w), make_float2(cv.x, cv.y), acc1[t]);
            acc0[t] = ffma2(make_float2(wb.x, wb.y), make_float2(cv.z, cv.w), acc0[t]);
            acc1[t] = ffma2(make_float2(wb.z, wb.w), make_float2(cv.z, cv.w), acc1[t]);
        }
    }
    __syncwarp();
#pragma unroll
    for (int t = 0; t < NT; t++) {
        float h0 = mishf(acc0[t].x + acc0[t].y);
        float h1 = mishf(acc1[t].x + acc1[t].y);
        cw[t * 64 + lane] = make_float2(h0, h1);    // h features 2l,2l+1 at k-position 2l
    }
    __syncwarp();
    float b20 = sm[12352 + 2 * lane], b21 = sm[12352 + 2 * lane + 1];
#pragma unroll
    for (int t = 0; t < NT; t++) { acc0[t] = make_float2(b20, 0.f); acc1[t] = make_float2(b21, 0.f); }
#pragma unroll 2
    for (int q = 0; q < 16; q++) {
        float4 wa = w2p[(2 * q) * 32 + lane];
        float4 wb = w2p[(2 * q + 1) * 32 + lane];
#pragma unroll
        for (int t = 0; t < NT; t++) {
            float4 cv = cw4[t * 32 + q];
            acc0[t] = ffma2(make_float2(wa.x, wa.y), make_float2(cv.x, cv.y), acc0[t]);
            acc1[t] = ffma2(make_float2(wa.z, wa.w), make_float2(cv.x, cv.y), acc1[t]);
            acc0[t] = ffma2(make_float2(wb.x, wb.y), make_float2(cv.z, cv.w), acc0[t]);
            acc1[t] = ffma2(make_float2(wb.z, wb.w), make_float2(cv.z, cv.w), acc1[t]);
        }
    }
#pragma unroll
    for (int t = 0; t < NT; t++)
        o[t] = make_float2(mishf(acc0[t].x + acc0[t].y), mishf(acc1[t].x + acc1[t].y));
}

// ======================= fused segment-reduce + MLP =======================
__global__ void __launch_bounds__(256, 2) fused_pass(
    const float* __restrict__ xsrc, const float* __restrict__ xtgt, int n_tgt,
    const int* __restrict__ ssrc, const int* __restrict__ offs, const int* __restrict__ cnt,
    const float* __restrict__ dotj,
    const float* __restrict__ eW, const float* __restrict__ eB,
    const float* __restrict__ w1, const float* __restrict__ b1,
    const float* __restrict__ w2, const float* __restrict__ b2,
    float* __restrict__ out) {
    extern __shared__ float sm[];
    float2* cats = reinterpret_cast<float2*>(sm + 12416);

    int tid = threadIdx.x;
    load_weights(sm, w1, b1, w2, b2, tid);
    __syncthreads();

    int warp = tid >> 5, lane = tid & 31;
    float wi0 = eW[2 * lane], wi1 = eW[2 * lane + 1];
    float bia = eB[0];
    float2* cw = cats + warp * NT * 64;
    int stride = gridDim.x * NWARP * NT;

    for (int base = (blockIdx.x * NWARP + warp) * NT; base < n_tgt; base += stride) {
        int nv = n_tgt - base; if (nv > NT) nv = NT;

        // Two NT/2 aggregation halves (keeps edge-loop register state at the NT=4 level)
#pragma unroll 1
        for (int half = 0; half < 2; half++) {
            int hb = half * NTH;
            int o[NTH], c[NTH];
            float2 xiv[NTH];
            float dot_i[NTH];
#pragma unroll
            for (int t = 0; t < NTH; t++) {
                bool v = (hb + t < nv);
                size_t node = (size_t)(base + hb + t);
                o[t] = v ? offs[node] : 0;
                c[t] = v ? cnt[node]  : 0;
                xiv[t] = v ? *reinterpret_cast<const float2*>(xtgt + node * F + 2 * lane)
                           : make_float2(0.f, 0.f);
                float p = xiv[t].x * wi0 + xiv[t].y * wi1;
#pragma unroll
                for (int off = 16; off; off >>= 1) p += __shfl_xor_sync(0xffffffffu, p, off);
                dot_i[t] = p + bia;
            }

            int maxc = c[0];
#pragma unroll
            for (int t = 1; t < NTH; t++) maxc = max(maxc, c[t]);

            float den0[NTH], num0[NTH], den1[NTH], num1[NTH];
#pragma unroll
            for (int t = 0; t < NTH; t++) { den0[t] = 0.f; num0[t] = 0.f; den1[t] = 0.f; num1[t] = 0.f; }

            for (int k = 0; k < maxc; k++) {
                float  djv[NTH];
                float2 xjv[NTH];
#pragma unroll
                for (int t = 0; t < NTH; t++) {
                    if (k < c[t]) {
                        int s = ssrc[o[t] + k];
                        djv[t] = dotj[s];
                        xjv[t] = *reinterpret_cast<const float2*>(xsrc + (size_t)s * F + 2 * lane);
                    }
                }
#pragma unroll
                for (int t = 0; t < NTH; t++) {
                    if (k < c[t]) {
                        float z = dot_i[t] + djv[t];
                        float w = __fdividef(1.f, 1.f + __expf(-z));
                        float m0 = w * xjv[t].x, m1 = w * xjv[t].y;
                        float e0 = __expf(m0),   e1 = __expf(m1);
                        den0[t] += e0; num0[t] += e0 * m0;
                        den1[t] += e1; num1[t] += e1 * m1;
                    }
                }
            }

#pragma unroll
            for (int t = 0; t < NTH; t++) {
                float a0 = __fdividef(num0[t], den0[t] + 1e-16f);
                float a1 = __fdividef(num1[t], den1[t] + 1e-16f);
                cw[(hb + t) * 64 + lane]      = make_float2(a0, a1);       // cat k=2l,2l+1
                cw[(hb + t) * 64 + 32 + lane] = xiv[t];                     // cat k=64+2l,65+2l
            }
        }
        __syncwarp();

        float2 ov[NT];
        mlp_apply(sm, cw, lane, ov);

#pragma unroll
        for (int t = 0; t < NT; t++) {
            if (t < nv) {
                *reinterpret_cast<float2*>(out + (size_t)(base + t) * F + 2 * lane) = ov[t];
            }
        }
        __syncwarp();
    }
}

// ======================= small-pass atomic path =======================

__global__ void edge_pass(const float* __restrict__ xsrc, const float* __restrict__ xtgt,
                          const int* __restrict__ src, const int* __restrict__ dst, int E,
                          const float* __restrict__ eW, const float* __restrict__ eB,
                          float* __restrict__ acc) {
    __shared__ float Ws[2 * F];
    __shared__ float Bs;
    int tid = threadIdx.x;
    if (tid < 2 * F) Ws[tid] = eW[tid];
    if (tid == 0) Bs = eB[0];
    __syncthreads();

    int lane = tid & 31;
    int e = blockIdx.x * (blockDim.x >> 5) + (tid >> 5);
    if (e >= E) return;

    int s = src[e], d = dst[e];
    float2 xj = *reinterpret_cast<const float2*>(xsrc + (size_t)s * F + 2 * lane);
    float2 xi = *reinterpret_cast<const float2*>(xtgt + (size_t)d * F + 2 * lane);

    float part = xi.x * Ws[2 * lane] + xi.y * Ws[2 * lane + 1]
               + xj.x * Ws[F + 2 * lane] + xj.y * Ws[F + 2 * lane + 1];
#pragma unroll
    for (int o = 16; o; o >>= 1) part += __shfl_xor_sync(0xffffffffu, part, o);

    float w = __fdividef(1.f, 1.f + __expf(-(part + Bs)));
    float m0 = w * xj.x, m1 = w * xj.y;
    float e0 = __expf(m0), e1 = __expf(m1);

    float4 v = make_float4(e0, e0 * m0, e1, e1 * m1);
    atomicAdd(reinterpret_cast<float4*>(acc + (size_t)d * 128 + 4 * lane), v);
}

__global__ void __launch_bounds__(256, 2) node_pass(
    const float* __restrict__ xtgt, int n_tgt,
    const float* __restrict__ w1, const float* __restrict__ b1,
    const float* __restrict__ w2, const float* __restrict__ b2,
    float* __restrict__ out, int accumulate, float* __restrict__ accbuf) {
    extern __shared__ float sm[];
    float2* cats = reinterpret_cast<float2*>(sm + 12416);

    int tid = threadIdx.x;
    load_weights(sm, w1, b1, w2, b2, tid);
    __syncthreads();

    int warp = tid >> 5, lane = tid & 31;
    float2* cw = cats + warp * NT * 64;
    int stride = gridDim.x * NWARP * NT;

    for (int base = (blockIdx.x * NWARP + warp) * NT; base < n_tgt; base += stride) {
        int nv = n_tgt - base; if (nv > NT) nv = NT;

#pragma unroll
        for (int t = 0; t < NT; t++) {
            if (t < nv) {
                size_t node = (size_t)(base + t);
                float4* ap = reinterpret_cast<float4*>(accbuf + node * 128 + 4 * lane);
                float4 a = *ap;
                *ap = make_float4(0.f, 0.f, 0.f, 0.f);  // self-clean for replay
                float2 xt = *reinterpret_cast<const float2*>(xtgt + node * F + 2 * lane);
                float a0 = __fdividef(a.y, a.x + 1e-16f);
                float a1 = __fdividef(a.w, a.z + 1e-16f);
                cw[t * 64 + lane]      = make_float2(a0, a1);
                cw[t * 64 + 32 + lane] = xt;
            } else {
                cw[t * 64 + lane]      = make_float2(0.f, 0.f);
                cw[t * 64 + 32 + lane] = make_float2(0.f, 0.f);
            }
        }
        __syncwarp();

        float2 ov[NT];
        mlp_apply(sm, cw, lane, ov);

#pragma unroll
        for (int t = 0; t < NT; t++) {
            if (t < nv) {
                float2* op = reinterpret_cast<float2*>(out + (size_t)(base + t) * F + 2 * lane);
                float2 o = ov[t];
                if (accumulate) { float2 pv = *op; o.x += pv.x; o.y += pv.y; }
                *op = o;
            }
        }
        __syncwarp();
    }
}

// ======================= launcher =======================

extern "C" void kernel_launch(void* const* d_in, const int* in_sizes, int n_in,
                              void* d_out, int out_size) {
    const float* x_hit = (const float*)d_in[0];
    const float* x_sp  = (const float*)d_in[1];
    const float* x_oph = (const float*)d_in[2];
    const float* x_pmt = (const float*)d_in[3];
    const float* x_opf = (const float*)d_in[4];
    const float* x_evt = (const float*)d_in[5];
    const float* ew = (const float*)d_in[6];
    const float* eb = (const float*)d_in[7];
    const float* w1 = (const float*)d_in[8];
    const float* b1 = (const float*)d_in[9];
    const float* w2 = (const float*)d_in[10];
    const float* b2 = (const float*)d_in[11];
    const int* e_hit_sp  = (const int*)d_in[12];
    const int* e_oph_pmt = (const int*)d_in[13];
    const int* e_pmt_opf = (const int*)d_in[14];
    const int* e_sp_evt  = (const int*)d_in[15];
    const int* e_opf_evt = (const int*)d_in[16];
    const int* e_evt_sp  = (const int*)d_in[17];
    const int* e_sp_hit  = (const int*)d_in[18];
    const int* e_evt_opf = (const int*)d_in[19];
    const int* e_opf_pmt = (const int*)d_in[20];
    const int* e_pmt_oph = (const int*)d_in[21];

    float* out = (float*)d_out;
    float* d_p   = out;
    float* d_n   = d_p   + (size_t)N_HIT * F;
    float* d_oph = d_n   + (size_t)N_SP  * F;
    float* d_pmt = d_oph + (size_t)N_OPH * F;
    float* d_opf = d_pmt + (size_t)N_PMT * F;
    float* d_i   = d_opf + (size_t)N_OPF * F;

    float *pacc, *pn, *ppmt, *popf, *pdotj;
    int *pcnt, *poffs, *pcur, *pssrc, *pbs;
    cudaGetSymbolAddress((void**)&pacc,  g_acc);
    cudaGetSymbolAddress((void**)&pn,    g_nbuf);
    cudaGetSymbolAddress((void**)&ppmt,  g_pmtbuf);
    cudaGetSymbolAddress((void**)&popf,  g_opfbuf);
    cudaGetSymbolAddress((void**)&pdotj, g_dotj);
    cudaGetSymbolAddress((void**)&pcnt,  g_count);
    cudaGetSymbolAddress((void**)&poffs, g_offs);
    cudaGetSymbolAddress((void**)&pcur,  g_cursor);
    cudaGetSymbolAddress((void**)&pssrc, g_ssrc);
    cudaGetSymbolAddress((void**)&pbs,   g_bsums);

    float* acc_opf = pacc;                          // p2, p7
    float* acc_evt = pacc + (size_t)N_OPF * 128;    // p3, p4

    const int SMEM = 82432;  // 12416 weight/bias floats + NWARP*NT*64 float2 (32KB)
    cudaFuncSetAttribute(node_pass,  cudaFuncAttributeMaxDynamicSharedMemorySize, SMEM);
    cudaFuncSetAttribute(fused_pass, cudaFuncAttributeMaxDynamicSharedMemorySize, SMEM);

    static cudaStream_t s1 = nullptr, s2 = nullptr;
    static cudaEvent_t evRoot = nullptr, evSA = nullptr, evB = nullptr, evD = nullptr,
                       evE = nullptr, evSB = nullptr, evF = nullptr;
    if (!s1) {
        int prLeast = 0, prGreatest = 0;
        cudaDeviceGetStreamPriorityRange(&prLeast, &prGreatest);
        cudaStreamCreateWithPriority(&s1, cudaStreamNonBlocking, prGreatest);  // critical compute
        cudaStreamCreateWithPriority(&s2, cudaStreamNonBlocking, prLeast);     // background sortB
        cudaEventCreateWithFlags(&evRoot, cudaEventDisableTiming);
        cudaEventCreateWithFlags(&evSA, cudaEventDisableTiming);
        cudaEventCreateWithFlags(&evB, cudaEventDisableTiming);
        cudaEventCreateWithFlags(&evD, cudaEventDisableTiming);
        cudaEventCreateWithFlags(&evE, cudaEventDisableTiming);
        cudaEventCreateWithFlags(&evSB, cudaEventDisableTiming);
        cudaEventCreateWithFlags(&evF, cudaEventDisableTiming);
    }
    cudaStream_t s0 = 0;

    int E0 = in_sizes[12] / 2;
    int E1 = in_sizes[13] / 2;
    int E2 = in_sizes[14] / 2;
    int E3 = in_sizes[15] / 2;
    int E4 = in_sizes[16] / 2;
    int E5 = in_sizes[17] / 2;
    int E6 = in_sizes[18] / 2;
    int E7 = in_sizes[19] / 2;
    int E8 = in_sizes[20] / 2;
    int E9 = in_sizes[21] / 2;

    // ---- sortA: p0,p1  /  sortB: p5,p6,p8,p9 ----
    int cb0 = 0, cb1 = N_SP, cb5 = cb1 + N_PMT, cb6 = cb5 + N_SP, cb8 = cb6 + N_HIT, cb9 = cb8 + N_PMT;
    int Ctot = cb9 + N_OPH;
    int CsplitA = cb5;

    SortCfg cfgA, cfgB;
    cfgA.src[0] = e_hit_sp;  cfgA.dst[0] = e_hit_sp + E0;  cfgA.cbase[0] = cb0;
    cfgA.src[1] = e_oph_pmt; cfgA.dst[1] = e_oph_pmt + E1; cfgA.cbase[1] = cb1;
    cfgA.ebase[0] = 0; cfgA.ebase[1] = E0; cfgA.ebase[2] = E0 + E1;
    cfgA.ebase[3] = cfgA.ebase[4] = 0x7fffffff;
    int EtotA = E0 + E1;

    cfgB.src[0] = e_evt_sp;  cfgB.dst[0] = e_evt_sp + E5;  cfgB.cbase[0] = cb5;
    cfgB.src[1] = e_sp_hit;  cfgB.dst[1] = e_sp_hit + E6;  cfgB.cbase[1] = cb6;
    cfgB.src[2] = e_opf_pmt; cfgB.dst[2] = e_opf_pmt + E8; cfgB.cbase[2] = cb8;
    cfgB.src[3] = e_pmt_oph; cfgB.dst[3] = e_pmt_oph + E9; cfgB.cbase[3] = cb9;
    cfgB.ebase[0] = 0; cfgB.ebase[1] = E5; cfgB.ebase[2] = E5 + E6;
    cfgB.ebase[3] = E5 + E6 + E8; cfgB.ebase[4] = E5 + E6 + E8 + E9;
    int EtotB = cfgB.ebase[4];

    int nbA = (CsplitA + SCHUNK - 1) / SCHUNK;
    int nbB = (Ctot - CsplitA + SCHUNK - 1) / SCHUNK;
    int* pbsA = pbs;
    int* pbsB = pbs + 16;

    const int db0 = 0, db1 = 300000, db5 = 500000, db6 = 501000, db8 = 551000, db9 = 553000;

    auto fused = [&](int i, const float* xs, const float* xt, int n_tgt,
                     int cb, int db, float* o, cudaStream_t st) {
        int fg = (n_tgt + NWARP * NT - 1) / (NWARP * NT); if (fg > 296) fg = 296;
        fused_pass<<<fg, 256, SMEM, st>>>(xs, xt, n_tgt, pssrc, poffs + cb, pcnt + cb,
                                          pdotj + db, ew + (size_t)i * 128, eb + i,
                                          w1 + (size_t)i * 8192, b1 + (size_t)i * 64,
                                          w2 + (size_t)i * 4096, b2 + (size_t)i * 64, o);
    };

    auto small = [&](int i, const float* xs, const float* xt, const int* e, int E,
                     int n_tgt, float* o, int accf, float* accbuf, cudaStream_t st) {
        int grid = (E + 15) / 16;
        edge_pass<<<grid, 512, 0, st>>>(xs, xt, e, e + E, E, ew + (size_t)i * 128, eb + i, accbuf);
        int ng = (n_tgt + NWARP * NT - 1) / (NWARP * NT); if (ng > 296) ng = 296;
        node_pass<<<ng, 256, SMEM, st>>>(xt, n_tgt, w1 + (size_t)i * 8192, b1 + (size_t)i * 64,
                                         w2 + (size_t)i * 4096, b2 + (size_t)i * 64,
                                         o, accf, accbuf);
    };

    // ==== fork: s1 (dotj), s2 (sortB, low priority) from root ====
    cudaEventRecord(evRoot, s0);
    cudaStreamWaitEvent(s1, evRoot, 0);
    cudaStreamWaitEvent(s2, evRoot, 0);

    // s0: sortA (critical path for phase 2)
    zero_k     <<<160, 256, 0, s0>>>(pcnt, CsplitA);
    hist_all   <<<(EtotA + 255) / 256, 256, 0, s0>>>(cfgA, EtotA, pcnt);
    scan1_k    <<<nbA, 256, 0, s0>>>(pcnt, 0, CsplitA, pbsA);
    scan2_k    <<<1, 128, 0, s0>>>(pbsA, nbA, 0);
    scan3_k    <<<nbA, 256, 0, s0>>>(pcnt, pbsA, 0, CsplitA, poffs, pcur);
    scatter_all<<<(EtotA + 255) / 256, 256, 0, s0>>>(cfgA, EtotA, pcur, pssrc);
    cudaEventRecord(evSA, s0);

    // s1: dotj for p0/p1
    dotj_k<<<(N_HIT + 7) / 8, 256, 0, s1>>>(x_hit, N_HIT, ew + 0 * 128, pdotj + db0);
    dotj_k<<<(N_OPH + 7) / 8, 256, 0, s1>>>(x_oph, N_OPH, ew + 1 * 128, pdotj + db1);
    cudaEventRecord(evB, s1);

    // s2: sortB (low priority, absolute offsets into g_ssrc)
    zero_k     <<<296, 256, 0, s2>>>(pcnt + CsplitA, Ctot - CsplitA);
    hist_all   <<<(EtotB + 255) / 256, 256, 0, s2>>>(cfgB, EtotB, pcnt);
    scan1_k    <<<nbB, 256, 0, s2>>>(pcnt, CsplitA, Ctot, pbsB);
    scan2_k    <<<1, 128, 0, s2>>>(pbsB, nbB, EtotA);
    scan3_k    <<<nbB, 256, 0, s2>>>(pcnt, pbsB, CsplitA, Ctot, poffs, pcur);
    scatter_all<<<(EtotB + 255) / 256, 256, 0, s2>>>(cfgB, EtotB, pcur, pssrc);
    cudaEventRecord(evSB, s2);

    // ==== Phase 2: {p0,p3} on s0  ∥  {p1,p2} on s1 ====
    cudaStreamWaitEvent(s0, evB, 0);
    cudaStreamWaitEvent(s1, evSA, 0);

    fused(0, x_hit, x_sp, N_SP, cb0, db0, pn, s0);                          // plane_to_nexus
    small(3, pn, x_evt, e_sp_evt, E3, N_EVT, d_i, 0, acc_evt, s0);          // nexus_to_interaction

    fused(1, x_oph, x_pmt, N_PMT, cb1, db1, ppmt, s1);                      // hit_to_pmt
    small(2, ppmt, x_opf, e_pmt_opf, E2, N_OPF, popf, 0, acc_opf, s1);      // pmt_to_flash
    cudaEventRecord(evD, s1);

    // ==== Phase 3: p4 (needs popf + d_i) on s0 ====
    cudaStreamWaitEvent(s0, evD, 0);
    small(4, popf, x_evt, e_opf_evt, E4, N_EVT, d_i, 1, acc_evt, s0);       // flash_to_interaction

    // ==== Phase 4: {dotj5,p5,dotj6,p6} on s0 ∥ {p7,dotj8,p8,dotj9,p9} on s1 ====
    cudaEventRecord(evE, s0);
    cudaStreamWaitEvent(s1, evE, 0);
    cudaStreamWaitEvent(s0, evSB, 0);
    cudaStreamWaitEvent(s1, evSB, 0);

    dotj_k<<<(N_EVT + 7) / 8, 256, 0, s0>>>(d_i, N_EVT, ew + 5 * 128, pdotj + db5);
    fused(5, d_i, pn, N_SP, cb5, db5, d_n, s0);                             // interaction_to_nexus
    dotj_k<<<(N_SP + 7) / 8, 256, 0, s0>>>(d_n, N_SP, ew + 6 * 128, pdotj + db6);
    fused(6, d_n, x_hit, N_HIT, cb6, db6, d_p, s0);                         // nexus_to_plane

    small(7, d_i, popf, e_evt_opf, E7, N_OPF, d_opf, 0, acc_opf, s1);       // interaction_to_flash
    dotj_k<<<(N_OPF + 7) / 8, 256, 0, s1>>>(d_opf, N_OPF, ew + 8 * 128, pdotj + db8);
    fused(8, d_opf, ppmt, N_PMT, cb8, db8, d_pmt, s1);                      // flash_to_pmt
    dotj_k<<<(N_PMT + 7) / 8, 256, 0, s1>>>(d_pmt, N_PMT, ew + 9 * 128, pdotj + db9);
    fused(9, d_pmt, x_oph, N_OPH, cb9, db9, d_oph, s1);                     // pmt_to_ophit

    cudaEventRecord(evF, s1);
    cudaStreamWaitEvent(s0, evF, 0);
}

// round 11
// speedup vs baseline: 1.4105x; 1.0437x over previous
#include <cuda_runtime.h>

#define F 64
#define NT 8
#define NTH 4              // aggregation half-width
#define NWARP 8            // 256-thread blocks

// Node counts (fixed by the problem)
#define N_HIT 300000
#define N_SP   50000
#define N_OPH 200000
#define N_PMT  30000
#define N_OPF   2000
#define N_EVT    256

#define CTOT 660000
#define ETOT 1510000
#define DTOT 600000

// ---- scratch (device globals) ----
__device__ float g_acc[(size_t)(N_OPF + N_EVT) * 128];
__device__ float g_nbuf[(size_t)N_SP * F];
__device__ float g_pmtbuf[(size_t)N_PMT * F];
__device__ float g_opfbuf[(size_t)N_OPF * F];
__device__ int   g_count[CTOT];
__device__ int   g_offs[CTOT];
__device__ int   g_cursor[CTOT];
__device__ int   g_ssrc[ETOT];
__device__ int   g_bsums[128];
__device__ float g_dotj[DTOT];

__device__ __forceinline__ float2 ffma2(float2 a, float2 b, float2 c) {
    unsigned long long ua = *reinterpret_cast<unsigned long long*>(&a);
    unsigned long long ub = *reinterpret_cast<unsigned long long*>(&b);
    unsigned long long uc = *reinterpret_cast<unsigned long long*>(&c);
    unsigned long long ud;
    asm("fma.rn.f32x2 %0, %1, %2, %3;" : "=l"(ud) : "l"(ua), "l"(ub), "l"(uc));
    return *reinterpret_cast<float2*>(&ud);
}

__device__ __forceinline__ float mishf(float x) {
    float e = __expf(fminf(x, 30.f));
    float t = e * (e + 2.f);
    return x * __fdividef(t, t + 2.f);
}

// ======================= batched sort machinery =======================

struct SortCfg {
    const int* src[4];
    const int* dst[4];
    int ebase[5];
    int cbase[4];
};

__global__ void zero_k(int* __restrict__ p, int n) {
    int i = blockIdx.x * blockDim.x + threadIdx.x;
    for (; i < n; i += gridDim.x * blockDim.x) p[i] = 0;
}

__global__ void hist_all(SortCfg cfg, int Etot, int* __restrict__ cnt) {
    int i = blockIdx.x * blockDim.x + threadIdx.x;
    if (i >= Etot) return;
    int s = 0;
    while (i >= cfg.ebase[s + 1]) s++;
    int li = i - cfg.ebase[s];
    atomicAdd(&cnt[cfg.cbase[s] + cfg.dst[s][li]], 1);
}

#define SCHUNK 8192
__global__ void scan1_k(const int* __restrict__ cnt, int cbeg, int cend, int* __restrict__ bsums) {
    __shared__ int ts[256];
    int tid = threadIdx.x;
    int base = cbeg + blockIdx.x * SCHUNK;
    int s = 0;
#pragma unroll
    for (int j = 0; j < 32; j++) {
        int i = base + j * 256 + tid;
        if (i < cend) s += cnt[i];
    }
    ts[tid] = s; __syncthreads();
    for (int o = 128; o; o >>= 1) { if (tid < o) ts[tid] += ts[tid + o]; __syncthreads(); }
    if (!tid) bsums[blockIdx.x] = ts[0];
}

__global__ void scan2_k(int* __restrict__ bsums, int nb, int base) {
    __shared__ int sb[128];
    int tid = threadIdx.x;
    if (tid < nb) sb[tid] = bsums[tid];
    __syncthreads();
    if (tid == 0) {
        int run = base;
        for (int b = 0; b < nb; b++) { int t = sb[b]; sb[b] = run; run += t; }
    }
    __syncthreads();
    if (tid < nb) bsums[tid] = sb[tid];
}

__global__ void scan3_k(const int* __restrict__ cnt, const int* __restrict__ bsums,
                        int cbeg, int cend, int* __restrict__ offs, int* __restrict__ cur) {
    __shared__ int ts[256];
    int tid = threadIdx.x;
    int base = cbeg + blockIdx.x * SCHUNK + tid * 32;
    int v[32]; int s = 0;
#pragma unroll
    for (int j = 0; j < 32; j++) {
        int i = base + j;
        v[j] = (i < cend) ? cnt[i] : 0;
        s += v[j];
    }
    ts[tid] = s; __syncthreads();
    for (int off = 1; off < 256; off <<= 1) {
        int add = (tid >= off) ? ts[tid - off] : 0;
        __syncthreads();
        ts[tid] += add;
        __syncthreads();
    }
    int run = (tid ? ts[tid - 1] : 0) + bsums[blockIdx.x];
#pragma unroll
    for (int j = 0; j < 32; j++) {
        int i = base + j;
        if (i < cend) { offs[i] = run; cur[i] = run; run += v[j]; }
    }
}

// cur holds ABSOLUTE positions into ssrc; writes are absolute.
__global__ void scatter_all(SortCfg cfg, int Etot, int* __restrict__ cur, int* __restrict__ ssrc) {
    int i = blockIdx.x * blockDim.x + threadIdx.x;
    if (i >= Etot) return;
    int s = 0;
    while (i >= cfg.ebase[s + 1]) s++;
    int li = i - cfg.ebase[s];
    int pos = atomicAdd(&cur[cfg.cbase[s] + cfg.dst[s][li]], 1);
    ssrc[pos] = cfg.src[s][li];
}

__global__ void dotj_k(const float* __restrict__ xsrc, int n_src,
                       const float* __restrict__ eW, float* __restrict__ dotj) {
    int lane = threadIdx.x & 31;
    int node = (blockIdx.x * blockDim.x + threadIdx.x) >> 5;
    float wj0 = eW[64 + 2 * lane], wj1 = eW[65 + 2 * lane];
    if (node >= n_src) return;
    float2 x = *reinterpret_cast<const float2*>(xsrc + (size_t)node * F + 2 * lane);
    float p = x.x * wj0 + x.y * wj1;
#pragma unroll
    for (int o = 16; o; o >>= 1) p += __shfl_xor_sync(0xffffffffu, p, o);
    if (!lane) dotj[node] = p;
}

// ======================= shared MLP helpers (K-pair FFMA2 layout) =======================
// smem floats: [0:8192) w1 packed, [8192:12288) w2 packed, [12288:12352) b1,
// [12352:12416) b2, [12416:20608) cat buffers (NWARP * NT * 64 float2 = 32KB).

__device__ __forceinline__ void load_weights(float* sm, const float* __restrict__ w1,
                                             const float* __restrict__ b1,
                                             const float* __restrict__ w2,
                                             const float* __restrict__ b2, int tid) {
    float4* w1p = reinterpret_cast<float4*>(sm);
    float4* w2p = reinterpret_cast<float4*>(sm + 8192);
    for (int e = tid; e < 2048; e += 256) {
        int kp = e >> 5, l = e & 31;
        const float* r0 = w1 + (size_t)(2 * kp) * 64 + 2 * l;
        const float* r1 = r0 + 64;
        w1p[e] = make_float4(r0[0], r1[0], r0[1], r1[1]);
    }
    for (int e = tid; e < 1024; e += 256) {
        int kp = e >> 5, l = e & 31;
        const float* r0 = w2 + (size_t)(2 * kp) * 64 + 2 * l;
        const float* r1 = r0 + 64;
        w2p[e] = make_float4(r0[0], r1[0], r0[1], r1[1]);
    }
    if (tid < 64) { sm[12288 + tid] = b1[tid]; sm[12352 + tid] = b2[tid]; }
}

__device__ __forceinline__ void mlp_apply(const float* sm, float2* cw, int lane, float2 o[NT]) {
    const float4* w1p = reinterpret_cast<const float4*>(sm);
    const float4* w2p = reinterpret_cast<const float4*>(sm + 8192);
    const float4* cw4 = reinterpret_cast<const float4*>(cw);
    float2 acc0[NT], acc1[NT];
    float b10 = sm[12288 + 2 * lane], b11 = sm[12288 + 2 * lane + 1];
#pragma unroll
    for (int t = 0; t < NT; t++) { acc0[t] = make_float2(b10, 0.f); acc1[t] = make_float2(b11, 0.f); }
#pragma unroll 2
    for (int q = 0; q < 32; q++) {
        float4 wa = w1p[(2 * q) * 32 + lane];
        float4 wb = w1p[(2 * q + 1) * 32 + lane];
#pragma unroll
        for (int t = 0; t < NT; t++) {
            float4 cv = cw4[t * 32 + q];
            acc0[t] = ffma2(make_float2(wa.x, wa.y), make_float2(cv.x, cv.y), acc0[t]);
            acc1[t] = ffma2(make_float2(wa.z, wa.w), make_float2(cv.x, cv.y), acc1[t]);
            acc0[t] = ffma2(make_float2(wb.x, wb.y), make_float2(cv.z, cv.w), acc0[t]);
            acc1[t] = ffma2(make_float2(wb.z, wb.w), make_float2(cv.z, cv.w), acc1[t]);
        }
    }
    __syncwarp();
#pragma unroll
    for (int t = 0; t < NT; t++) {
        float h0 = mishf(acc0[t].x + acc0[t].y);
        float h1 = mishf(acc1[t].x + acc1[t].y);
        cw[t * 64 + lane] = make_float2(h0, h1);
    }
    __syncwarp();
    float b20 = sm[12352 + 2 * lane], b21 = sm[12352 + 2 * lane + 1];
#pragma unroll
    for (int t = 0; t < NT; t++) { acc0[t] = make_float2(b20, 0.f); acc1[t] = make_float2(b21, 0.f); }
#pragma unroll 2
    for (int q = 0; q < 16; q++) {
        float4 wa = w2p[(2 * q) * 32 + lane];
        float4 wb = w2p[(2 * q + 1) * 32 + lane];
#pragma unroll
        for (int t = 0; t < NT; t++) {
            float4 cv = cw4[t * 32 + q];
            acc0[t] = ffma2(make_float2(wa.x, wa.y), make_float2(cv.x, cv.y), acc0[t]);
            acc1[t] = ffma2(make_float2(wa.z, wa.w), make_float2(cv.x, cv.y), acc1[t]);
            acc0[t] = ffma2(make_float2(wb.x, wb.y), make_float2(cv.z, cv.w), acc0[t]);
            acc1[t] = ffma2(make_float2(wb.z, wb.w), make_float2(cv.z, cv.w), acc1[t]);
        }
    }
#pragma unroll
    for (int t = 0; t < NT; t++)
        o[t] = make_float2(mishf(acc0[t].x + acc0[t].y), mishf(acc1[t].x + acc1[t].y));
}

// Fused dotj epilogue: dot(out_node, djW_j-half) per node, warp-reduced, lane0 stores.
__device__ __forceinline__ void dotj_epilogue(const float2 ov[NT], int base, int nv, int lane,
                                              float wd0, float wd1, float* __restrict__ djOut) {
#pragma unroll
    for (int t = 0; t < NT; t++) {
        float p = ov[t].x * wd0 + ov[t].y * wd1;
#pragma unroll
        for (int off = 16; off; off >>= 1) p += __shfl_xor_sync(0xffffffffu, p, off);
        if (!lane && t < nv) djOut[base + t] = p;
    }
}

// ======================= fused segment-reduce + MLP =======================
__global__ void __launch_bounds__(256, 2) fused_pass(
    const float* __restrict__ xsrc, const float* __restrict__ xtgt, int n_tgt,
    const int* __restrict__ ssrc, const int* __restrict__ offs, const int* __restrict__ cnt,
    const float* __restrict__ dotj,
    const float* __restrict__ eW, const float* __restrict__ eB,
    const float* __restrict__ w1, const float* __restrict__ b1,
    const float* __restrict__ w2, const float* __restrict__ b2,
    float* __restrict__ out,
    const float* __restrict__ djW, float* __restrict__ djOut) {
    extern __shared__ float sm[];
    float2* cats = reinterpret_cast<float2*>(sm + 12416);

    int tid = threadIdx.x;
    load_weights(sm, w1, b1, w2, b2, tid);
    __syncthreads();

    int warp = tid >> 5, lane = tid & 31;
    float wi0 = eW[2 * lane], wi1 = eW[2 * lane + 1];
    float bia = eB[0];
    float wd0 = 0.f, wd1 = 0.f;
    if (djOut) { wd0 = djW[64 + 2 * lane]; wd1 = djW[65 + 2 * lane]; }
    float2* cw = cats + warp * NT * 64;
    int stride = gridDim.x * NWARP * NT;

    for (int base = (blockIdx.x * NWARP + warp) * NT; base < n_tgt; base += stride) {
        int nv = n_tgt - base; if (nv > NT) nv = NT;

        // Two NT/2 aggregation halves (keeps edge-loop register state low)
#pragma unroll 1
        for (int half = 0; half < 2; half++) {
            int hb = half * NTH;
            int o[NTH], c[NTH];
            float2 xiv[NTH];
            float dot_i[NTH];
#pragma unroll
            for (int t = 0; t < NTH; t++) {
                bool v = (hb + t < nv);
                size_t node = (size_t)(base + hb + t);
                o[t] = v ? offs[node] : 0;
                c[t] = v ? cnt[node]  : 0;
                xiv[t] = v ? *reinterpret_cast<const float2*>(xtgt + node * F + 2 * lane)
                           : make_float2(0.f, 0.f);
                float p = xiv[t].x * wi0 + xiv[t].y * wi1;
#pragma unroll
                for (int off = 16; off; off >>= 1) p += __shfl_xor_sync(0xffffffffu, p, off);
                dot_i[t] = p + bia;
            }

            int maxc = c[0];
#pragma unroll
            for (int t = 1; t < NTH; t++) maxc = max(maxc, c[t]);

            float den0[NTH], num0[NTH], den1[NTH], num1[NTH];
#pragma unroll
            for (int t = 0; t < NTH; t++) { den0[t] = 0.f; num0[t] = 0.f; den1[t] = 0.f; num1[t] = 0.f; }

            // Software-pipelined edge loop: ssrc index prefetched one iteration ahead.
            int sv[NTH];
#pragma unroll
            for (int t = 0; t < NTH; t++) sv[t] = (0 < c[t]) ? ssrc[o[t]] : 0;

            for (int k = 0; k < maxc; k++) {
                int snx[NTH];
#pragma unroll
                for (int t = 0; t < NTH; t++)
                    snx[t] = (k + 1 < c[t]) ? ssrc[o[t] + k + 1] : 0;

                float  djv[NTH];
                float2 xjv[NTH];
#pragma unroll
                for (int t = 0; t < NTH; t++) {
                    if (k < c[t]) {
                        djv[t] = dotj[sv[t]];
                        xjv[t] = *reinterpret_cast<const float2*>(xsrc + (size_t)sv[t] * F + 2 * lane);
                    }
                }
#pragma unroll
                for (int t = 0; t < NTH; t++) {
                    if (k < c[t]) {
                        float z = dot_i[t] + djv[t];
                        float w = __fdividef(1.f, 1.f + __expf(-z));
                        float m0 = w * xjv[t].x, m1 = w * xjv[t].y;
                        float e0 = __expf(m0),   e1 = __expf(m1);
                        den0[t] += e0; num0[t] += e0 * m0;
                        den1[t] += e1; num1[t] += e1 * m1;
                    }
                    sv[t] = snx[t];
                }
            }

#pragma unroll
            for (int t = 0; t < NTH; t++) {
                float a0 = __fdividef(num0[t], den0[t] + 1e-16f);
                float a1 = __fdividef(num1[t], den1[t] + 1e-16f);
                cw[(hb + t) * 64 + lane]      = make_float2(a0, a1);
                cw[(hb + t) * 64 + 32 + lane] = xiv[t];
            }
        }
        __syncwarp();

        float2 ov[NT];
        mlp_apply(sm, cw, lane, ov);

#pragma unroll
        for (int t = 0; t < NT; t++) {
            if (t < nv) {
                *reinterpret_cast<float2*>(out + (size_t)(base + t) * F + 2 * lane) = ov[t];
            }
        }
        if (djOut) dotj_epilogue(ov, base, nv, lane, wd0, wd1, djOut);
        __syncwarp();
    }
}

// ======================= small-pass atomic path =======================

__global__ void edge_pass(const float* __restrict__ xsrc, const float* __restrict__ xtgt,
                          const int* __restrict__ src, const int* __restrict__ dst, int E,
                          const float* __restrict__ eW, const float* __restrict__ eB,
                          float* __restrict__ acc) {
    __shared__ float Ws[2 * F];
    __shared__ float Bs;
    int tid = threadIdx.x;
    if (tid < 2 * F) Ws[tid] = eW[tid];
    if (tid == 0) Bs = eB[0];
    __syncthreads();

    int lane = tid & 31;
    int e = blockIdx.x * (blockDim.x >> 5) + (tid >> 5);
    if (e >= E) return;

    int s = src[e], d = dst[e];
    float2 xj = *reinterpret_cast<const float2*>(xsrc + (size_t)s * F + 2 * lane);
    float2 xi = *reinterpret_cast<const float2*>(xtgt + (size_t)d * F + 2 * lane);

    float part = xi.x * Ws[2 * lane] + xi.y * Ws[2 * lane + 1]
               + xj.x * Ws[F + 2 * lane] + xj.y * Ws[F + 2 * lane + 1];
#pragma unroll
    for (int o = 16; o; o >>= 1) part += __shfl_xor_sync(0xffffffffu, part, o);

    float w = __fdividef(1.f, 1.f + __expf(-(part + Bs)));
    float m0 = w * xj.x, m1 = w * xj.y;
    float e0 = __expf(m0), e1 = __expf(m1);

    float4 v = make_float4(e0, e0 * m0, e1, e1 * m1);
    atomicAdd(reinterpret_cast<float4*>(acc + (size_t)d * 128 + 4 * lane), v);
}

__global__ void __launch_bounds__(256, 2) node_pass(
    const float* __restrict__ xtgt, int n_tgt,
    const float* __restrict__ w1, const float* __restrict__ b1,
    const float* __restrict__ w2, const float* __restrict__ b2,
    float* __restrict__ out, int accumulate, float* __restrict__ accbuf,
    const float* __restrict__ djW, float* __restrict__ djOut) {
    extern __shared__ float sm[];
    float2* cats = reinterpret_cast<float2*>(sm + 12416);

    int tid = threadIdx.x;
    load_weights(sm, w1, b1, w2, b2, tid);
    __syncthreads();

    int warp = tid >> 5, lane = tid & 31;
    float wd0 = 0.f, wd1 = 0.f;
    if (djOut) { wd0 = djW[64 + 2 * lane]; wd1 = djW[65 + 2 * lane]; }
    float2* cw = cats + warp * NT * 64;
    int stride = gridDim.x * NWARP * NT;

    for (int base = (blockIdx.x * NWARP + warp) * NT; base < n_tgt; base += stride) {
        int nv = n_tgt - base; if (nv > NT) nv = NT;

#pragma unroll
        for (int t = 0; t < NT; t++) {
            if (t < nv) {
                size_t node = (size_t)(base + t);
                float4* ap = reinterpret_cast<float4*>(accbuf + node * 128 + 4 * lane);
                float4 a = *ap;
                *ap = make_float4(0.f, 0.f, 0.f, 0.f);  // self-clean for replay
                float2 xt = *reinterpret_cast<const float2*>(xtgt + node * F + 2 * lane);
                float a0 = __fdividef(a.y, a.x + 1e-16f);
                float a1 = __fdividef(a.w, a.z + 1e-16f);
                cw[t * 64 + lane]      = make_float2(a0, a1);
                cw[t * 64 + 32 + lane] = xt;
            } else {
                cw[t * 64 + lane]      = make_float2(0.f, 0.f);
                cw[t * 64 + 32 + lane] = make_float2(0.f, 0.f);
            }
        }
        __syncwarp();

        float2 ov[NT];
        mlp_apply(sm, cw, lane, ov);

#pragma unroll
        for (int t = 0; t < NT; t++) {
            if (t < nv) {
                float2* op = reinterpret_cast<float2*>(out + (size_t)(base + t) * F + 2 * lane);
                float2 o = ov[t];
                if (accumulate) { float2 pv = *op; o.x += pv.x; o.y += pv.y; }
                *op = o;
                ov[t] = o;   // dotj must see the accumulated value
            }
        }
        if (djOut) dotj_epilogue(ov, base, nv, lane, wd0, wd1, djOut);
        __syncwarp();
    }
}

// ======================= launcher =======================

extern "C" void kernel_launch(void* const* d_in, const int* in_sizes, int n_in,
                              void* d_out, int out_size) {
    const float* x_hit = (const float*)d_in[0];
    const float* x_sp  = (const float*)d_in[1];
    const float* x_oph = (const float*)d_in[2];
    const float* x_pmt = (const float*)d_in[3];
    const float* x_opf = (const float*)d_in[4];
    const float* x_evt = (const float*)d_in[5];
    const float* ew = (const float*)d_in[6];
    const float* eb = (const float*)d_in[7];
    const float* w1 = (const float*)d_in[8];
    const float* b1 = (const float*)d_in[9];
    const float* w2 = (const float*)d_in[10];
    const float* b2 = (const float*)d_in[11];
    const int* e_hit_sp  = (const int*)d_in[12];
    const int* e_oph_pmt = (const int*)d_in[13];
    const int* e_pmt_opf = (const int*)d_in[14];
    const int* e_sp_evt  = (const int*)d_in[15];
    const int* e_opf_evt = (const int*)d_in[16];
    const int* e_evt_sp  = (const int*)d_in[17];
    const int* e_sp_hit  = (const int*)d_in[18];
    const int* e_evt_opf = (const int*)d_in[19];
    const int* e_opf_pmt = (const int*)d_in[20];
    const int* e_pmt_oph = (const int*)d_in[21];

    float* out = (float*)d_out;
    float* d_p   = out;
    float* d_n   = d_p   + (size_t)N_HIT * F;
    float* d_oph = d_n   + (size_t)N_SP  * F;
    float* d_pmt = d_oph + (size_t)N_OPH * F;
    float* d_opf = d_pmt + (size_t)N_PMT * F;
    float* d_i   = d_opf + (size_t)N_OPF * F;

    float *pacc, *pn, *ppmt, *popf, *pdotj;
    int *pcnt, *poffs, *pcur, *pssrc, *pbs;
    cudaGetSymbolAddress((void**)&pacc,  g_acc);
    cudaGetSymbolAddress((void**)&pn,    g_nbuf);
    cudaGetSymbolAddress((void**)&ppmt,  g_pmtbuf);
    cudaGetSymbolAddress((void**)&popf,  g_opfbuf);
    cudaGetSymbolAddress((void**)&pdotj, g_dotj);
    cudaGetSymbolAddress((void**)&pcnt,  g_count);
    cudaGetSymbolAddress((void**)&poffs, g_offs);
    cudaGetSymbolAddress((void**)&pcur,  g_cursor);
    cudaGetSymbolAddress((void**)&pssrc, g_ssrc);
    cudaGetSymbolAddress((void**)&pbs,   g_bsums);

    float* acc_opf = pacc;                          // p2, p7
    float* acc_evt = pacc + (size_t)N_OPF * 128;    // p3, p4

    const int SMEM = 82432;
    cudaFuncSetAttribute(node_pass,  cudaFuncAttributeMaxDynamicSharedMemorySize, SMEM);
    cudaFuncSetAttribute(fused_pass, cudaFuncAttributeMaxDynamicSharedMemorySize, SMEM);

    static cudaStream_t s1 = nullptr, s2 = nullptr;
    static cudaEvent_t evRoot = nullptr, evSA = nullptr, evB = nullptr, evD = nullptr,
                       evE = nullptr, evSB = nullptr, evF = nullptr;
    if (!s1) {
        int prLeast = 0, prGreatest = 0;
        cudaDeviceGetStreamPriorityRange(&prLeast, &prGreatest);
        cudaStreamCreateWithPriority(&s1, cudaStreamNonBlocking, prGreatest);  // critical compute
        cudaStreamCreateWithPriority(&s2, cudaStreamNonBlocking, prLeast);     // background sortB
        cudaEventCreateWithFlags(&evRoot, cudaEventDisableTiming);
        cudaEventCreateWithFlags(&evSA, cudaEventDisableTiming);
        cudaEventCreateWithFlags(&evB, cudaEventDisableTiming);
        cudaEventCreateWithFlags(&evD, cudaEventDisableTiming);
        cudaEventCreateWithFlags(&evE, cudaEventDisableTiming);
        cudaEventCreateWithFlags(&evSB, cudaEventDisableTiming);
        cudaEventCreateWithFlags(&evF, cudaEventDisableTiming);
    }
    cudaStream_t s0 = 0;

    int E0 = in_sizes[12] / 2;
    int E1 = in_sizes[13] / 2;
    int E2 = in_sizes[14] / 2;
    int E3 = in_sizes[15] / 2;
    int E4 = in_sizes[16] / 2;
    int E5 = in_sizes[17] / 2;
    int E6 = in_sizes[18] / 2;
    int E7 = in_sizes[19] / 2;
    int E8 = in_sizes[20] / 2;
    int E9 = in_sizes[21] / 2;

    // ---- sortA: p0,p1  /  sortB: p5,p6,p8,p9 ----
    int cb0 = 0, cb1 = N_SP, cb5 = cb1 + N_PMT, cb6 = cb5 + N_SP, cb8 = cb6 + N_HIT, cb9 = cb8 + N_PMT;
    int Ctot = cb9 + N_OPH;
    int CsplitA = cb5;

    SortCfg cfgA, cfgB;
    cfgA.src[0] = e_hit_sp;  cfgA.dst[0] = e_hit_sp + E0;  cfgA.cbase[0] = cb0;
    cfgA.src[1] = e_oph_pmt; cfgA.dst[1] = e_oph_pmt + E1; cfgA.cbase[1] = cb1;
    cfgA.ebase[0] = 0; cfgA.ebase[1] = E0; cfgA.ebase[2] = E0 + E1;
    cfgA.ebase[3] = cfgA.ebase[4] = 0x7fffffff;
    int EtotA = E0 + E1;

    cfgB.src[0] = e_evt_sp;  cfgB.dst[0] = e_evt_sp + E5;  cfgB.cbase[0] = cb5;
    cfgB.src[1] = e_sp_hit;  cfgB.dst[1] = e_sp_hit + E6;  cfgB.cbase[1] = cb6;
    cfgB.src[2] = e_opf_pmt; cfgB.dst[2] = e_opf_pmt + E8; cfgB.cbase[2] = cb8;
    cfgB.src[3] = e_pmt_oph; cfgB.dst[3] = e_pmt_oph + E9; cfgB.cbase[3] = cb9;
    cfgB.ebase[0] = 0; cfgB.ebase[1] = E5; cfgB.ebase[2] = E5 + E6;
    cfgB.ebase[3] = E5 + E6 + E8; cfgB.ebase[4] = E5 + E6 + E8 + E9;
    int EtotB = cfgB.ebase[4];

    int nbA = (CsplitA + SCHUNK - 1) / SCHUNK;
    int nbB = (Ctot - CsplitA + SCHUNK - 1) / SCHUNK;
    int* pbsA = pbs;
    int* pbsB = pbs + 16;

    const int db0 = 0, db1 = 300000, db5 = 500000, db6 = 501000, db8 = 551000, db9 = 553000;

    auto fused = [&](int i, const float* xs, const float* xt, int n_tgt,
                     int cb, int db, float* o, cudaStream_t st,
                     const float* djW, float* djOut) {
        int fg = (n_tgt + NWARP * NT - 1) / (NWARP * NT); if (fg > 296) fg = 296;
        fused_pass<<<fg, 256, SMEM, st>>>(xs, xt, n_tgt, pssrc, poffs + cb, pcnt + cb,
                                          pdotj + db, ew + (size_t)i * 128, eb + i,
                                          w1 + (size_t)i * 8192, b1 + (size_t)i * 64,
                                          w2 + (size_t)i * 4096, b2 + (size_t)i * 64, o,
                                          djW, djOut);
    };

    auto small = [&](int i, const float* xs, const float* xt, const int* e, int E,
                     int n_tgt, float* o, int accf, float* accbuf, cudaStream_t st,
                     const float* djW, float* djOut) {
        int grid = (E + 15) / 16;
        edge_pass<<<grid, 512, 0, st>>>(xs, xt, e, e + E, E, ew + (size_t)i * 128, eb + i, accbuf);
        int ng = (n_tgt + NWARP * NT - 1) / (NWARP * NT); if (ng > 296) ng = 296;
        node_pass<<<ng, 256, SMEM, st>>>(xt, n_tgt, w1 + (size_t)i * 8192, b1 + (size_t)i * 64,
                                         w2 + (size_t)i * 4096, b2 + (size_t)i * 64,
                                         o, accf, accbuf, djW, djOut);
    };

    // ==== fork: s1 (dotj), s2 (sortB, low priority) from root ====
    cudaEventRecord(evRoot, s0);
    cudaStreamWaitEvent(s1, evRoot, 0);
    cudaStreamWaitEvent(s2, evRoot, 0);

    // s0: sortA (critical path for phase 2)
    zero_k     <<<160, 256, 0, s0>>>(pcnt, CsplitA);
    hist_all   <<<(EtotA + 255) / 256, 256, 0, s0>>>(cfgA, EtotA, pcnt);
    scan1_k    <<<nbA, 256, 0, s0>>>(pcnt, 0, CsplitA, pbsA);
    scan2_k    <<<1, 128, 0, s0>>>(pbsA, nbA, 0);
    scan3_k    <<<nbA, 256, 0, s0>>>(pcnt, pbsA, 0, CsplitA, poffs, pcur);
    scatter_all<<<(EtotA + 255) / 256, 256, 0, s0>>>(cfgA, EtotA, pcur, pssrc);
    cudaEventRecord(evSA, s0);

    // s1: dotj for p0/p1
    dotj_k<<<(N_HIT + 7) / 8, 256, 0, s1>>>(x_hit, N_HIT, ew + 0 * 128, pdotj + db0);
    dotj_k<<<(N_OPH + 7) / 8, 256, 0, s1>>>(x_oph, N_OPH, ew + 1 * 128, pdotj + db1);
    cudaEventRecord(evB, s1);

    // s2: sortB (low priority, absolute offsets into g_ssrc)
    zero_k     <<<296, 256, 0, s2>>>(pcnt + CsplitA, Ctot - CsplitA);
    hist_all   <<<(EtotB + 255) / 256, 256, 0, s2>>>(cfgB, EtotB, pcnt);
    scan1_k    <<<nbB, 256, 0, s2>>>(pcnt, CsplitA, Ctot, pbsB);
    scan2_k    <<<1, 128, 0, s2>>>(pbsB, nbB, EtotA);
    scan3_k    <<<nbB, 256, 0, s2>>>(pcnt, pbsB, CsplitA, Ctot, poffs, pcur);
    scatter_all<<<(EtotB + 255) / 256, 256, 0, s2>>>(cfgB, EtotB, pcur, pssrc);
    cudaEventRecord(evSB, s2);

    // ==== Phase 2: {p0,p3} on s0  ∥  {p1,p2} on s1 ====
    cudaStreamWaitEvent(s0, evB, 0);
    cudaStreamWaitEvent(s1, evSA, 0);

    fused(0, x_hit, x_sp, N_SP, cb0, db0, pn, s0, nullptr, nullptr);            // plane_to_nexus
    small(3, pn, x_evt, e_sp_evt, E3, N_EVT, d_i, 0, acc_evt, s0,
          nullptr, nullptr);                                                     // nexus_to_interaction

    fused(1, x_oph, x_pmt, N_PMT, cb1, db1, ppmt, s1, nullptr, nullptr);        // hit_to_pmt
    small(2, ppmt, x_opf, e_pmt_opf, E2, N_OPF, popf, 0, acc_opf, s1,
          nullptr, nullptr);                                                     // pmt_to_flash
    cudaEventRecord(evD, s1);

    // ==== Phase 3: p4 (needs popf + d_i) on s0; fused dotj5 epilogue ====
    cudaStreamWaitEvent(s0, evD, 0);
    small(4, popf, x_evt, e_opf_evt, E4, N_EVT, d_i, 1, acc_evt, s0,
          ew + 5 * 128, pdotj + db5);                                            // flash_to_interaction

    // ==== Phase 4: {p5,p6} on s0 ∥ {p7,p8,p9} on s1 — dotj fused into producers ====
    cudaEventRecord(evE, s0);
    cudaStreamWaitEvent(s1, evE, 0);
    cudaStreamWaitEvent(s0, evSB, 0);
    cudaStreamWaitEvent(s1, evSB, 0);

    fused(5, d_i, pn, N_SP, cb5, db5, d_n, s0, ew + 6 * 128, pdotj + db6);      // interaction_to_nexus
    fused(6, d_n, x_hit, N_HIT, cb6, db6, d_p, s0, nullptr, nullptr);           // nexus_to_plane

    small(7, d_i, popf, e_evt_opf, E7, N_OPF, d_opf, 0, acc_opf, s1,
          ew + 8 * 128, pdotj + db8);                                            // interaction_to_flash
    fused(8, d_opf, ppmt, N_PMT, cb8, db8, d_pmt, s1, ew + 9 * 128, pdotj + db9); // flash_to_pmt
    fused(9, d_pmt, x_oph, N_OPH, cb9, db9, d_oph, s1, nullptr, nullptr);       // pmt_to_ophit

    cudaEventRecord(evF, s1);
    cudaStreamWaitEvent(s0, evF, 0);
}